// round 9
// baseline (speedup 1.0000x reference)
#include <cuda_runtime.h>
#include <math.h>

// ---------------- problem constants (fixed by setup_inputs) ----------------
#define H   200
#define DT  48
#define DA  6
#define TT  20
#define BB  32768
#define CF  10

// ---------------- tiling ----------------
#define MT       64     // batch rows per block
#define NTHREADS 512    // 16 warps -> 4 per SMSP

// padded GEMM dims (k-major packed weights)
// stage1 A rows: pad(8) + x1(48) + h1(200)              = 256
// stage2 A rows: h1'(200) + tiled(48) + h2(200)         = 448
// stage3 A rows: pad(8) + x1(48) + h2'(200)             = 256  (reuses AsX)
// stage4 A rows: out3 padded                            = 224
#define K1 256
#define N1 1024         // 256 units * 4 gates (200 real)
#define K2 448
#define N2 1024
#define K3 256
#define N3 256          // fc1 out padded (200 real)
#define K4 224
#define N4 64           // fc2 out padded (48 real)

#define ASX_ROWS 256
#define AS2_ROWS 448
#define WS_FLOATS (32 * 256)
#define SMEM_FLOATS (ASX_ROWS*MT + AS2_ROWS*MT + WS_FLOATS)
#define SMEM_BYTES  (SMEM_FLOATS * 4)

typedef unsigned long long u64;

// ---------------- device scratch (no runtime allocation allowed) ----------
__device__ float g_WA[K1 * N1];
__device__ float g_WB[K2 * N2];
__device__ float g_WC[K3 * N3];
__device__ float g_WD[K4 * N4];
__device__ float g_bb1[N1];
__device__ float g_bb2[N2];
__device__ float g_b1p[N3];
__device__ float g_b2p[N4];
// h1, c1, h2, c2 each stored [H][B] (unit-major for coalesced staging)
__device__ float g_hc[(size_t)4 * H * BB];
// feedback x1 (previous out4), stored [DT][B]
__device__ float g_x1fb[(size_t)DT * BB];

// ---------------- fast transcendentals (ex2/rcp approx, ~1e-7 abs err) ----
__device__ __forceinline__ float fex2(float x) {
    float r; asm("ex2.approx.f32 %0, %1;" : "=f"(r) : "f"(x)); return r;
}
__device__ __forceinline__ float frcp(float x) {
    float r; asm("rcp.approx.f32 %0, %1;" : "=f"(r) : "f"(x)); return r;
}
#define L2E 1.4426950408889634f
__device__ __forceinline__ float sigf(float x) {
    return frcp(1.f + fex2(-L2E * x));
}
__device__ __forceinline__ float tanhff(float x) {
    return fmaf(2.f, frcp(1.f + fex2(-2.f * L2E * x)), -1.f);
}

// ---------------- packed f32x2 helpers ------------------------------------
__device__ __forceinline__ u64 pk2(float lo, float hi) {
    u64 r; asm("mov.b64 %0, {%1,%2};" : "=l"(r) : "f"(lo), "f"(hi)); return r;
}
__device__ __forceinline__ float2 up2(u64 v) {
    float2 r; asm("mov.b64 {%0,%1}, %2;" : "=f"(r.x), "=f"(r.y) : "l"(v)); return r;
}
__device__ __forceinline__ void ffma2(u64& d, u64 a, u64 b) {
    asm("fma.rn.f32x2 %0, %1, %2, %0;" : "+l"(d) : "l"(a), "l"(b));
}

// ---------------- weight repack kernel (runs once per kernel_launch) ------
__global__ void prep_kernel(
    const float* __restrict__ Wih1, const float* __restrict__ Whh1,
    const float* __restrict__ bih1, const float* __restrict__ bhh1,
    const float* __restrict__ Wih2, const float* __restrict__ Whh2,
    const float* __restrict__ bih2, const float* __restrict__ bhh2,
    const float* __restrict__ W1,   const float* __restrict__ b1,
    const float* __restrict__ W2,   const float* __restrict__ b2)
{
    int idx    = blockIdx.x * blockDim.x + threadIdx.x;
    int stride = gridDim.x * blockDim.x;

    // WA: [K1][N1] k-major, gate-interleaved cols: col = u*4+g
    // k-order: pad(8), x1(48), h1(200)
    for (int i = idx; i < K1 * N1; i += stride) {
        int k = i / N1, col = i % N1;
        int u = col >> 2, g = col & 3;
        float v = 0.f;
        if (u < H) {
            int row = g * H + u;
            if (k >= 8 && k < 8 + DT)            v = Wih1[row * DT + (k - 8)];
            else if (k >= 56 && k < 56 + H)      v = Whh1[row * H + (k - 56)];
        }
        g_WA[i] = v;
    }
    // WB: [K2][N2]; A-order = [h1'(200), tiled(48), h2(200)]
    for (int i = idx; i < K2 * N2; i += stride) {
        int k = i / N2, col = i % N2;
        int u = col >> 2, g = col & 3;
        float v = 0.f;
        if (u < H) {
            int row = g * H + u;
            if (k < H + DT) v = Wih2[row * (H + DT) + k];
            else            v = Whh2[row * H + (k - (H + DT))];
        }
        g_WB[i] = v;
    }
    // WC: [K3][N3]; A-order = [pad(8), x1(48), h2'(200)];
    // W1 cols ordered [h2(200), x1(48)]
    for (int i = idx; i < K3 * N3; i += stride) {
        int k = i / N3, n = i % N3;
        float v = 0.f;
        if (n < H) {
            if (k >= 8 && k < 8 + DT)        v = W1[n * (H + DT) + H + (k - 8)];
            else if (k >= 56 && k < 56 + H)  v = W1[n * (H + DT) + (k - 56)];
        }
        g_WC[i] = v;
    }
    // WD: [K4][N4]
    for (int i = idx; i < K4 * N4; i += stride) {
        int k = i / N4, n = i % N4;
        float v = 0.f;
        if (n < DT && k < H) v = W2[n * H + k];
        g_WD[i] = v;
    }
    // biases
    for (int i = idx; i < N1; i += stride) {
        int u = i >> 2, g = i & 3;
        float v1 = 0.f, v2 = 0.f;
        if (u < H) {
            v1 = bih1[g * H + u] + bhh1[g * H + u];
            v2 = bih2[g * H + u] + bhh2[g * H + u];
        }
        g_bb1[i] = v1;
        g_bb2[i] = v2;
    }
    for (int i = idx; i < N3; i += stride) g_b1p[i] = (i < H)  ? b1[i] : 0.f;
    for (int i = idx; i < N4; i += stride) g_b2p[i] = (i < DT) ? b2[i] : 0.f;
}

__global__ void zero_hc_kernel() {
    size_t n = (size_t)4 * H * BB;
    for (size_t i = blockIdx.x * (size_t)blockDim.x + threadIdx.x; i < n;
         i += (size_t)gridDim.x * blockDim.x)
        g_hc[i] = 0.f;
}

// ---------------- block GEMM pass (f32x2 packed) --------------------------
// A: smem [K][MT] k-major. Wg: global [K][ldw] k-major. Computes 64*CPT
// columns starting at colBase. Thread owns rows m0..m0+7 (4 f32x2 pairs)
// and cols cg*CPT..cg*CPT+CPT-1. All 32 lanes of a warp share m0 -> A loads
// are warp-broadcast; W loads are 16B/lane conflict-free.
template <int CPT>
__device__ __forceinline__ void gemm_pass(
    const float* __restrict__ A, const float* __restrict__ Wg,
    int K, int ldw, int colBase, float* __restrict__ Ws,
    u64 (&acc)[4][CPT], int m0, int cg, int tid)
{
    constexpr int NC = 64 * CPT;
    constexpr int LD_ITERS = NC / 64;   // (32*NC) / (NTHREADS*4)

#pragma unroll
    for (int i = 0; i < 4; i++)
#pragma unroll
        for (int j = 0; j < CPT; j++) acc[i][j] = 0ULL;

    for (int k0 = 0; k0 < K; k0 += 32) {
        __syncthreads();  // Ws reuse + prior smem writes visible
#pragma unroll
        for (int it = 0; it < LD_ITERS; it++) {
            int idx = tid * 4 + it * (NTHREADS * 4);
            int kk = idx / NC, c = idx % NC;
            *(float4*)(Ws + idx) =
                *(const float4*)(Wg + (size_t)(k0 + kk) * ldw + colBase + c);
        }
        __syncthreads();
#pragma unroll
        for (int kk = 0; kk < 32; kk++) {
            const float* Ar = A + (k0 + kk) * MT + m0;
            double2 q0 = *(const double2*)(Ar + 0);
            double2 q1 = *(const double2*)(Ar + 4);
            u64 ap[4] = {
                __double_as_longlong(q0.x), __double_as_longlong(q0.y),
                __double_as_longlong(q1.x), __double_as_longlong(q1.y)};
            u64 wp[CPT];
            const float* Wr = Ws + kk * NC + cg * CPT;
            if (CPT == 4) {
                float4 wv = *(const float4*)Wr;
                wp[0] = pk2(wv.x, wv.x); wp[1] = pk2(wv.y, wv.y);
                wp[2] = pk2(wv.z, wv.z); wp[3] = pk2(wv.w, wv.w);
            } else {
                float wv = Wr[0];
                wp[0] = pk2(wv, wv);
            }
#pragma unroll
            for (int i = 0; i < 4; i++)
#pragma unroll
                for (int j = 0; j < CPT; j++) ffma2(acc[i][j], ap[i], wp[j]);
        }
    }
}

// ---------------- LSTM gate epilogue (one unit, 8 rows) -------------------
__device__ __forceinline__ void lstm_epi(
    u64 (&acc)[4][4], const float* __restrict__ bb,
    float* __restrict__ cgl, float* __restrict__ hgl,
    float* __restrict__ hdst, int u, int row0, int m0)
{
    float4 b = *(const float4*)(bb + u * 4);  // i,f,g,o
    size_t base = (size_t)u * BB + row0 + m0;
#pragma unroll
    for (int i = 0; i < 4; i++) {
        float2 zi = up2(acc[i][0]);
        float2 zf = up2(acc[i][1]);
        float2 zg = up2(acc[i][2]);
        float2 zo = up2(acc[i][3]);
        float2 c = *(const float2*)(cgl + base + 2 * i);
        float cx = sigf(zf.x + b.y) * c.x + sigf(zi.x + b.x) * tanhff(zg.x + b.z);
        float cy = sigf(zf.y + b.y) * c.y + sigf(zi.y + b.x) * tanhff(zg.y + b.z);
        float hx = sigf(zo.x + b.w) * tanhff(cx);
        float hy = sigf(zo.y + b.w) * tanhff(cy);
        *(float2*)(cgl + base + 2 * i) = make_float2(cx, cy);
        *(float2*)(hgl + base + 2 * i) = make_float2(hx, hy);
        *(float2*)(hdst + u * MT + m0 + 2 * i) = make_float2(hx, hy);
    }
}

// ---------------- fused per-timestep kernel -------------------------------
__global__ void __launch_bounds__(NTHREADS, 1)
step_kernel(const float* __restrict__ tact, const float* __restrict__ act,
            float* __restrict__ out, int t, int outFrame, int useFb)
{
    extern __shared__ float sm[];
    float* AsX = sm;                      // [256][MT]
    float* As2 = sm + ASX_ROWS * MT;      // [448][MT]
    float* Ws  = As2 + AS2_ROWS * MT;     // [32][256]

    int tid  = threadIdx.x;
    int w    = tid >> 5, lane = tid & 31;
    int m0   = (w & 7) * 8;               // row group (8 rows, 4 pairs)
    int cg   = ((w >> 3) << 5) + lane;    // col group 0..63
    int row0 = blockIdx.x * MT;

    float* h1g = g_hc;
    float* c1g = g_hc + (size_t)1 * H * BB;
    float* h2g = g_hc + (size_t)2 * H * BB;
    float* c2g = g_hc + (size_t)3 * H * BB;

    // -------- stage A operands --------
    // AsX rows 0..8 = 0 (pad)
    for (int idx = tid; idx < 8 * MT; idx += NTHREADS) AsX[idx] = 0.f;
    // AsX rows 8..56 = x1 (tactile or feedback)
    for (int idx = tid; idx < DT * MT; idx += NTHREADS) {
        int d = idx / MT, r = idx % MT;
        float v = useFb ? g_x1fb[(size_t)d * BB + row0 + r]
                        : tact[(size_t)t * BB * DT + (size_t)(row0 + r) * DT + d];
        AsX[(8 + d) * MT + r] = v;
    }
    // AsX rows 56..256 = h1
    for (int idx = tid; idx < H * MT; idx += NTHREADS) {
        int u = idx / MT, r = idx % MT;
        AsX[(56 + u) * MT + r] = h1g[(size_t)u * BB + row0 + r];
    }
    // As2 rows 200..248 = tiled(act) = [a(6), state(6)] x4
    for (int idx = tid; idx < DT * MT; idx += NTHREADS) {
        int j = idx / MT, r = idx % MT;
        int jm = j % 12;
        float v = (jm < 6)
            ? act[(size_t)(t + 1) * BB * DA + (size_t)(row0 + r) * DA + jm]
            : act[(size_t)(row0 + r) * DA + (jm - 6)];
        As2[(H + j) * MT + r] = v;
    }
    // As2 rows 248..448 = h2
    for (int idx = tid; idx < H * MT; idx += NTHREADS) {
        int u = idx / MT, r = idx % MT;
        As2[(H + DT + u) * MT + r] = h2g[(size_t)u * BB + row0 + r];
    }

    u64 acc[4][4];

    // -------- stage 1: z1 GEMM + LSTM1 gates (h1' -> As2 rows 0..200) -----
    for (int p = 0; p < 4; p++) {
        gemm_pass<4>(AsX, g_WA, K1, N1, p * 256, Ws, acc, m0, cg, tid);
        int u = p * 64 + cg;
        if (u < H) lstm_epi(acc, g_bb1, c1g, h1g, As2, u, row0, m0);
    }

    // -------- stage 2: z2 GEMM + LSTM2 gates (h2' -> AsX rows 56..256) ----
    for (int p = 0; p < 4; p++) {
        gemm_pass<4>(As2, g_WB, K2, N2, p * 256, Ws, acc, m0, cg, tid);
        int u = p * 64 + cg;
        if (u < H) lstm_epi(acc, g_bb2, c2g, h2g, AsX + 56 * MT, u, row0, m0);
    }

    // -------- stage 3: fc1 + tanh (out3 -> As2 rows 0..224) ---------------
    gemm_pass<4>(AsX, g_WC, K3, N3, 0, Ws, acc, m0, cg, tid);
#pragma unroll
    for (int j = 0; j < 4; j++) {
        int n = cg * 4 + j;
        if (n < K4) {   // rows 200..224 get exact zeros (zero W cols, zero bias)
            float b = g_b1p[n];
#pragma unroll
            for (int i = 0; i < 4; i++) {
                float2 z = up2(acc[i][j]);
                *(float2*)(As2 + n * MT + m0 + 2 * i) =
                    make_float2(tanhff(z.x + b), tanhff(z.y + b));
            }
        }
    }

    // -------- stage 4: fc2 + tanh, write outputs --------------------------
    u64 acc1[4][1];
    gemm_pass<1>(As2, g_WD, K4, N4, 0, Ws, acc1, m0, cg, tid);
    {
        int n = cg;
        if (n < DT) {
            float b = g_b2p[n];
#pragma unroll
            for (int i = 0; i < 4; i++) {
                float2 z = up2(acc1[i][0]);
                float vx = tanhff(z.x + b);
                float vy = tanhff(z.y + b);
                int rg = row0 + m0 + 2 * i;
                *(float2*)(g_x1fb + (size_t)n * BB + rg) = make_float2(vx, vy);
                if (outFrame >= 0) {
                    out[((size_t)outFrame * BB + rg) * DT + n]     = vx;
                    out[((size_t)outFrame * BB + rg + 1) * DT + n] = vy;
                }
            }
        }
    }
}

// ---------------- host launcher -----------------------------------------
extern "C" void kernel_launch(void* const* d_in, const int* in_sizes, int n_in,
                              void* d_out, int out_size) {
    const float* tactiles = (const float*)d_in[0];
    const float* actions  = (const float*)d_in[1];
    const float* Wih1 = (const float*)d_in[2];
    const float* Whh1 = (const float*)d_in[3];
    const float* bih1 = (const float*)d_in[4];
    const float* bhh1 = (const float*)d_in[5];
    const float* Wih2 = (const float*)d_in[6];
    const float* Whh2 = (const float*)d_in[7];
    const float* bih2 = (const float*)d_in[8];
    const float* bhh2 = (const float*)d_in[9];
    const float* W1   = (const float*)d_in[10];
    const float* b1   = (const float*)d_in[11];
    const float* W2   = (const float*)d_in[12];
    const float* b2   = (const float*)d_in[13];
    float* out = (float*)d_out;

    cudaFuncSetAttribute(step_kernel,
                         cudaFuncAttributeMaxDynamicSharedMemorySize, SMEM_BYTES);

    zero_hc_kernel<<<2048, 256>>>();
    prep_kernel<<<512, 256>>>(Wih1, Whh1, bih1, bhh1,
                              Wih2, Whh2, bih2, bhh2, W1, b1, W2, b2);

    for (int t = 0; t < TT - 1; t++) {
        int useFb    = (t >= CF) ? 1 : 0;
        int outFrame = (t >= CF - 1) ? (t - (CF - 1)) : -1;
        step_kernel<<<BB / MT, NTHREADS, SMEM_BYTES>>>(
            tactiles, actions, out, t, outFrame, useFb);
    }
}

// round 11
// speedup vs baseline: 1.8050x; 1.8050x over previous
#include <cuda_runtime.h>
#include <stdint.h>

#define H 200
#define DT 48
#define DA 6
#define TT 20
#define BB 32768
#define CF 10
#define MT 64
#define NCTA 512
#define NTH 256

typedef unsigned int u32;

// ---------------- device globals (no runtime alloc) ----------------
// fragment-order weight images
__device__ float g_WAf[4 * 32 * 32 * 64];   // stage1: 4 panels, 32 kc, 32 ntl
__device__ float g_WBf[4 * 56 * 32 * 64];   // stage2
__device__ float g_WCf[32 * 32 * 64];       // stage3
__device__ float g_WDf[28 * 8 * 64];        // stage4 (64 cols)
__device__ float g_bb1[1024], g_bb2[1024], g_b1p[256], g_b2p[64];
__device__ float g_h1[(size_t)H * BB];
__device__ float g_h2[(size_t)H * BB];
__device__ float g_c1[(size_t)H * BB];
__device__ float g_c2[(size_t)H * BB];
__device__ float g_x1fb[(size_t)DT * BB];

// ---------------- scalar helpers ----------------
__device__ __forceinline__ float fex2(float x){ float r; asm("ex2.approx.f32 %0,%1;":"=f"(r):"f"(x)); return r; }
__device__ __forceinline__ float frcp(float x){ float r; asm("rcp.approx.f32 %0,%1;":"=f"(r):"f"(x)); return r; }
#define L2E 1.4426950408889634f
__device__ __forceinline__ float sigf(float x){ return frcp(1.f + fex2(-L2E*x)); }
__device__ __forceinline__ float tanhff(float x){ return fmaf(2.f, frcp(1.f + fex2(-2.f*L2E*x)), -1.f); }
__device__ __forceinline__ float t32(float x){ u32 r; asm("cvt.rna.tf32.f32 %0,%1;":"=r"(r):"f"(x)); return __uint_as_float(r); }

// A fragment layout: [kc][mc(4)][lane(32)][slot(4)]
// element (k, m): lane=(m&7)*4+(k&3), slot=((m>>3)&1)+2*((k>>2)&1)
__device__ __forceinline__ int aidx(int k, int m){
    int kc = k >> 3, kk = k & 7, mc = m >> 4, mm = m & 15;
    return ((kc*4 + mc)*32 + (mm&7)*4 + (kk&3))*4 + (mm>>3) + 2*(kk>>2);
}

// tf32 m16n8k8 mma, accumulate in place
__device__ __forceinline__ void mma8(float (&d)[4], const u32 (&a)[4], const u32 (&b)[2]){
    asm volatile("mma.sync.aligned.m16n8k8.row.col.f32.tf32.tf32.f32 "
        "{%0,%1,%2,%3}, {%4,%5,%6,%7}, {%8,%9}, {%0,%1,%2,%3};"
        : "+f"(d[0]), "+f"(d[1]), "+f"(d[2]), "+f"(d[3])
        : "r"(a[0]), "r"(a[1]), "r"(a[2]), "r"(a[3]), "r"(b[0]), "r"(b[1]));
}

// ---------------- init / prep ----------------
__global__ void zero_state(){
    size_t st = (size_t)gridDim.x*blockDim.x;
    size_t id = (size_t)blockIdx.x*blockDim.x + threadIdx.x;
    for (size_t i=id; i<(size_t)H*BB; i+=st){ g_h1[i]=0.f; g_h2[i]=0.f; g_c1[i]=0.f; g_c2[i]=0.f; }
}

// W fragment layout: [((p*kcTot+kc)*ntlTot+ntl)*32 + lane]*2 + slot
// element (k, col): lane=(col&7)*4+(k&3), slot=(k>>2)&1, ntl=col>>3, kc=k>>3
__global__ void prep(
    const float* __restrict__ Wih1, const float* __restrict__ Whh1,
    const float* __restrict__ bih1, const float* __restrict__ bhh1,
    const float* __restrict__ Wih2, const float* __restrict__ Whh2,
    const float* __restrict__ bih2, const float* __restrict__ bhh2,
    const float* __restrict__ W1,   const float* __restrict__ b1,
    const float* __restrict__ W2,   const float* __restrict__ b2)
{
    int st = gridDim.x*blockDim.x, id = blockIdx.x*blockDim.x + threadIdx.x;
    // WA: 4 panels x 32 kc x 32 ntl ; cols gate-interleaved (col=u*4+g over 1024)
    for (int i=id; i<4*32*32*64; i+=st){
        int slot=i&1, lane=(i>>1)&31, ntl=(i>>6)&31, kc=(i>>11)&31, p=i>>16;
        int k = kc*8 + 4*slot + (lane&3);
        int C = p*256 + ntl*8 + (lane>>2);
        int u = C>>2, g = C&3; float v = 0.f;
        if (u < H){
            int row = g*H + u;
            if (k >= 8 && k < 56)      v = Wih1[row*DT + k-8];
            else if (k >= 56)          v = Whh1[row*H + k-56];
        }
        g_WAf[i] = t32(v);
    }
    // WB: 4 x 56 kc x 32 ntl ; A k-order [h1'(200), tiled(48), h2(200)]
    for (int i=id; i<4*56*32*64; i+=st){
        int slot=i&1, lane=(i>>1)&31, ntl=(i>>6)&31, rest=i>>11;
        int kc = rest % 56, p = rest / 56;
        int k = kc*8 + 4*slot + (lane&3);
        int C = p*256 + ntl*8 + (lane>>2);
        int u = C>>2, g = C&3; float v = 0.f;
        if (u < H){
            int row = g*H + u;
            if (k < 248) v = Wih2[row*248 + k];
            else         v = Whh2[row*H + k-248];
        }
        g_WBf[i] = t32(v);
    }
    // WC: 32 kc x 32 ntl ; A k-order [pad8, x1(48)->W1 col 200.., h2'(200)->W1 col 0..]
    for (int i=id; i<32*32*64; i+=st){
        int slot=i&1, lane=(i>>1)&31, ntl=(i>>6)&31, kc=(i>>11)&31;
        int k = kc*8 + 4*slot + (lane&3);
        int n = ntl*8 + (lane>>2); float v = 0.f;
        if (n < H){
            if (k >= 8 && k < 56)  v = W1[n*248 + 200 + (k-8)];
            else if (k >= 56)      v = W1[n*248 + (k-56)];
        }
        g_WCf[i] = t32(v);
    }
    // WD: 28 kc x 8 ntl (64 cols) ; k = out3 index
    for (int i=id; i<28*8*64; i+=st){
        int slot=i&1, lane=(i>>1)&31, ntl=(i>>6)&7, kc=i>>9;
        int k = kc*8 + 4*slot + (lane&3);
        int n = ntl*8 + (lane>>2);
        float v = (n < DT && k < H) ? W2[n*H + k] : 0.f;
        g_WDf[i] = t32(v);
    }
    // biases
    for (int i=id; i<1024; i+=st){
        int u=i>>2, g=i&3; float v1=0.f, v2=0.f;
        if (u < H){ v1 = bih1[g*H+u]+bhh1[g*H+u]; v2 = bih2[g*H+u]+bhh2[g*H+u]; }
        g_bb1[i]=v1; g_bb2[i]=v2;
    }
    for (int i=id; i<256; i+=st) g_b1p[i] = (i<H)? b1[i] : 0.f;
    for (int i=id; i<64;  i+=st) g_b2p[i] = (i<DT)? b2[i] : 0.f;
}

// ---------------- panel GEMM: stream W chunks, warp mma ----------------
template <int NT>
__device__ __forceinline__ void panel_mma(
    const float* __restrict__ Asm, const float* __restrict__ Wg,
    float* __restrict__ Ws, int nkc, int ntlTot,
    float (&acc)[NT][4], int mc, int ncBase, int tid, int lane, bool active)
{
#pragma unroll
    for (int j=0; j<NT; j++){ acc[j][0]=0.f; acc[j][1]=0.f; acc[j][2]=0.f; acc[j][3]=0.f; }
    int chunkFl = 4*ntlTot*64;
    int nch = nkc >> 2;
    for (int c=0; c<nch; c++){
        __syncthreads();
        for (int i=tid*4; i<chunkFl; i+=NTH*4)
            *(float4*)(Ws+i) = *(const float4*)(Wg + (size_t)c*chunkFl + i);
        __syncthreads();
        if (active){
#pragma unroll
            for (int kcl=0; kcl<4; kcl++){
                int kc = c*4 + kcl;
                float4 av = *(const float4*)(Asm + ((kc*4 + mc)*32 + lane)*4);
                u32 a[4] = {__float_as_uint(av.x), __float_as_uint(av.y),
                            __float_as_uint(av.z), __float_as_uint(av.w)};
#pragma unroll
                for (int j=0; j<NT; j++){
                    int ntl = ncBase + j;
                    float2 bv = *(const float2*)(Ws + ((kcl*ntlTot + ntl)*32 + lane)*2);
                    u32 b[2] = {__float_as_uint(bv.x), __float_as_uint(bv.y)};
                    mma8(acc[j], a, b);
                }
            }
        }
    }
}

// ---------------- LSTM epilogue (warp tile 16x128, gate-interleaved) ------
__device__ __forceinline__ void epi_lstm(
    float (&acc)[16][4], int p, int nc2, int mc,
    const float* __restrict__ bb, float* __restrict__ cG, float* __restrict__ hG,
    float* __restrict__ smDst, int kOff, int row0, int lane)
{
    int rbase = mc*16 + (lane>>2);
    int odd = lane & 1;
#pragma unroll
    for (int j=0; j<16; j++){
        float e0 = __shfl_xor_sync(0xFFFFFFFFu, acc[j][0], 1);
        float e1 = __shfl_xor_sync(0xFFFFFFFFu, acc[j][1], 1);
        float e2 = __shfl_xor_sync(0xFFFFFFFFu, acc[j][2], 1);
        float e3 = __shfl_xor_sync(0xFFFFFFFFu, acc[j][3], 1);
        float zi = odd ? e2 : acc[j][0];
        float zf = odd ? e3 : acc[j][1];
        float zg = odd ? acc[j][2] : e0;
        float zo = odd ? acc[j][3] : e1;
        int r = rbase + (odd ? 8 : 0);
        int u = p*64 + nc2*32 + j*2 + ((lane&3)>>1);
        if (u < H){
            float4 b = *(const float4*)(bb + u*4);     // i,f,g,o
            size_t gix = (size_t)u*BB + row0 + r;
            float c = cG[gix];
            float cn = sigf(zf + b.y)*c + sigf(zi + b.x)*tanhff(zg + b.z);
            float hn = sigf(zo + b.w)*tanhff(cn);
            cG[gix] = cn; hG[gix] = hn;
            smDst[aidx(kOff + u, r)] = t32(hn);
        }
    }
}

// ---------------- fused per-timestep kernel -------------------------------
__global__ void __launch_bounds__(NTH, 1)
step_kernel(const float* __restrict__ tact, const float* __restrict__ act,
            float* __restrict__ out, int t, int outFrame, int useFb)
{
    extern __shared__ __align__(16) float sm[];
    float* AsX = sm;                 // 256k x 64m frag = 16384 floats
    float* As2 = sm + 16384;         // 448k x 64m frag = 28672 floats
    float* Ws  = sm + 16384 + 28672; // up to 8192 floats

    int tid = threadIdx.x, w = tid>>5, lane = tid&31;
    int mc = w & 3, nc2 = w >> 2;
    int row0 = blockIdx.x * MT;

    // -------- staging (t32-rounded) --------
    for (int i=tid; i<512; i+=NTH) AsX[i] = 0.f;   // kc0 pad = zeros
    if (useFb){
        for (int i=tid; i<DT*MT; i+=NTH){
            int d=i>>6, r=i&63;
            AsX[aidx(8+d, r)] = t32(g_x1fb[(size_t)d*BB + row0 + r]);
        }
    } else {
        for (int i=tid; i<DT*MT; i+=NTH){
            int d=i>>6, r=i&63;
            AsX[aidx(8+d, r)] = t32(tact[((size_t)t*BB + row0 + r)*DT + d]);
        }
    }
    for (int i=tid; i<H*MT; i+=NTH){
        int u=i>>6, r=i&63;
        AsX[aidx(56+u, r)] = t32(g_h1[(size_t)u*BB + row0 + r]);
    }
    for (int i=tid; i<DT*MT; i+=NTH){
        int j=i>>6, r=i&63, jm=j%12;
        size_t row = (size_t)row0 + r;
        float v = (jm<6) ? act[((size_t)(t+1)*BB + row)*DA + jm]
                         : act[row*DA + jm - 6];
        As2[aidx(200+j, r)] = t32(v);
    }
    for (int i=tid; i<H*MT; i+=NTH){
        int u=i>>6, r=i&63;
        As2[aidx(248+u, r)] = t32(g_h2[(size_t)u*BB + row0 + r]);
    }

    float acc[16][4];

    // -------- stage 1: z1 + LSTM1 (h1' -> As2 k=u) --------
    for (int p=0; p<4; p++){
        panel_mma<16>(AsX, g_WAf + (size_t)p*32*32*64, Ws, 32, 32,
                      acc, mc, nc2*16, tid, lane, true);
        epi_lstm(acc, p, nc2, mc, g_bb1, g_c1, g_h1, As2, 0, row0, lane);
    }
    // -------- stage 2: z2 + LSTM2 (h2' -> AsX k=56+u) --------
    for (int p=0; p<4; p++){
        panel_mma<16>(As2, g_WBf + (size_t)p*56*32*64, Ws, 56, 32,
                      acc, mc, nc2*16, tid, lane, true);
        epi_lstm(acc, p, nc2, mc, g_bb2, g_c2, g_h2, AsX, 56, row0, lane);
    }
    // -------- stage 3: fc1 + tanh (out3 -> As2 k=n) --------
    {
        panel_mma<16>(AsX, g_WCf, Ws, 32, 32, acc, mc, nc2*16, tid, lane, true);
        int r = mc*16 + (lane>>2);
#pragma unroll
        for (int j=0; j<16; j++){
            int nb = nc2*128 + j*8 + (lane&3)*2;
#pragma unroll
            for (int q=0; q<4; q++){
                int n = nb + (q&1);
                int rr = r + (q>>1)*8;
                if (n < 224)
                    As2[aidx(n, rr)] = t32(tanhff(acc[j][q] + g_b1p[n]));
            }
        }
    }
    // -------- stage 4: fc2 + tanh -> out + feedback --------
    {
        float acc4[8][4];
        panel_mma<8>(As2, g_WDf, Ws, 28, 8, acc4, w, 0, tid, lane, w < 4);
        if (w < 4){
            int r = w*16 + (lane>>2);
#pragma unroll
            for (int j=0; j<8; j++){
                int nb = j*8 + (lane&3)*2;
#pragma unroll
                for (int q=0; q<4; q++){
                    int n = nb + (q&1);
                    int rr = r + (q>>1)*8;
                    if (n < DT){
                        float v = tanhff(acc4[j][q] + g_b2p[n]);
                        size_t grow = (size_t)row0 + rr;
                        if (outFrame >= 0)
                            out[((size_t)outFrame*BB + grow)*DT + n] = v;
                        g_x1fb[(size_t)n*BB + grow] = v;
                    }
                }
            }
        }
    }
}

// ---------------- host launcher -------------------------------------------
#define SMEM_BYTES ((16384 + 28672 + 8192) * 4)

extern "C" void kernel_launch(void* const* d_in, const int* in_sizes, int n_in,
                              void* d_out, int out_size) {
    const float* tactiles = (const float*)d_in[0];
    const float* actions  = (const float*)d_in[1];
    const float* Wih1 = (const float*)d_in[2];
    const float* Whh1 = (const float*)d_in[3];
    const float* bih1 = (const float*)d_in[4];
    const float* bhh1 = (const float*)d_in[5];
    const float* Wih2 = (const float*)d_in[6];
    const float* Whh2 = (const float*)d_in[7];
    const float* bih2 = (const float*)d_in[8];
    const float* bhh2 = (const float*)d_in[9];
    const float* W1   = (const float*)d_in[10];
    const float* b1   = (const float*)d_in[11];
    const float* W2   = (const float*)d_in[12];
    const float* b2   = (const float*)d_in[13];
    float* out = (float*)d_out;

    cudaFuncSetAttribute(step_kernel,
        cudaFuncAttributeMaxDynamicSharedMemorySize, SMEM_BYTES);

    zero_state<<<2048, 256>>>();
    prep<<<512, 256>>>(Wih1, Whh1, bih1, bhh1,
                       Wih2, Whh2, bih2, bhh2, W1, b1, W2, b2);

    for (int t = 0; t < TT - 1; t++) {
        int useFb    = (t >= CF) ? 1 : 0;
        int outFrame = (t >= CF - 1) ? (t - (CF - 1)) : -1;
        step_kernel<<<NCTA, NTH, SMEM_BYTES>>>(
            tactiles, actions, out, t, outFrame, useFb);
    }
}

// round 12
// speedup vs baseline: 1.9700x; 1.0914x over previous
#include <cuda_runtime.h>
#include <stdint.h>

#define H 200
#define DT 48
#define DA 6
#define TT 20
#define BB 32768
#define CF 10
#define MT 64
#define NCTA 512
#define NTH 512

typedef unsigned int u32;

// ---------------- device globals (no runtime alloc) ----------------
// pair-packed fragment-order weight images
__device__ float g_WAf[4 * 32 * 32 * 64];   // [p][kc32][np16][lane32][e4]
__device__ float g_WBf[4 * 56 * 32 * 64];   // [p][kc56][np16][lane32][e4]
__device__ float g_WCf[32 * 32 * 64];       // [kc32][np16][lane32][e4]
__device__ float g_WDf[28 * 8 * 64];        // [kc28][np4][lane32][e4]
__device__ float g_bb1[1024], g_bb2[1024], g_b1p[256], g_b2p[64];
__device__ float g_h1[(size_t)H * BB];
__device__ float g_h2[(size_t)H * BB];
__device__ float g_c1[(size_t)H * BB];
__device__ float g_c2[(size_t)H * BB];
__device__ float g_x1fb[(size_t)DT * BB];

// ---------------- scalar helpers ----------------
__device__ __forceinline__ float fex2(float x){ float r; asm("ex2.approx.f32 %0,%1;":"=f"(r):"f"(x)); return r; }
__device__ __forceinline__ float frcp(float x){ float r; asm("rcp.approx.f32 %0,%1;":"=f"(r):"f"(x)); return r; }
#define L2E 1.4426950408889634f
__device__ __forceinline__ float sigf(float x){ return frcp(1.f + fex2(-L2E*x)); }
__device__ __forceinline__ float tanhff(float x){ return fmaf(2.f, frcp(1.f + fex2(-2.f*L2E*x)), -1.f); }
__device__ __forceinline__ float t32(float x){ u32 r; asm("cvt.rna.tf32.f32 %0,%1;":"=r"(r):"f"(x)); return __uint_as_float(r); }

// A fragment layout: [kc][mc(4)][lane(32)][slot(4)]
// element (k, m): lane=(m&7)*4+(k&3), slot=((m>>3)&1)+2*((k>>2)&1)
__device__ __forceinline__ int aidx(int k, int m){
    int kc = k >> 3, kk = k & 7, mc = m >> 4, mm = m & 15;
    return ((kc*4 + mc)*32 + (mm&7)*4 + (kk&3))*4 + (mm>>3) + 2*(kk>>2);
}

// tf32 m16n8k8 mma, accumulate in place
__device__ __forceinline__ void mma8(float (&d)[4], const u32 (&a)[4], u32 b0, u32 b1){
    asm volatile("mma.sync.aligned.m16n8k8.row.col.f32.tf32.tf32.f32 "
        "{%0,%1,%2,%3}, {%4,%5,%6,%7}, {%8,%9}, {%0,%1,%2,%3};"
        : "+f"(d[0]), "+f"(d[1]), "+f"(d[2]), "+f"(d[3])
        : "r"(a[0]), "r"(a[1]), "r"(a[2]), "r"(a[3]), "r"(b0), "r"(b1));
}

// ---------------- init / prep ----------------
__global__ void zero_state(){
    size_t st = (size_t)gridDim.x*blockDim.x;
    size_t id = (size_t)blockIdx.x*blockDim.x + threadIdx.x;
    for (size_t i=id; i<(size_t)H*BB; i+=st){ g_h1[i]=0.f; g_h2[i]=0.f; g_c1[i]=0.f; g_c2[i]=0.f; }
}

// W pair-packed layout: index = (((kc*(ntlTot/2)+np)*32+lane)*4 + e)
// ntl = np*2 + (e>>1), slot = e&1; element (k,col): k = kc*8+4*slot+(lane&3),
// col = ntl*8 + (lane>>2)
__global__ void prep(
    const float* __restrict__ Wih1, const float* __restrict__ Whh1,
    const float* __restrict__ bih1, const float* __restrict__ bhh1,
    const float* __restrict__ Wih2, const float* __restrict__ Whh2,
    const float* __restrict__ bih2, const float* __restrict__ bhh2,
    const float* __restrict__ W1,   const float* __restrict__ b1,
    const float* __restrict__ W2,   const float* __restrict__ b2)
{
    int st = gridDim.x*blockDim.x, id = blockIdx.x*blockDim.x + threadIdx.x;
    // WA: [p][kc32][np16][lane][e]; cols gate-interleaved (col=u*4+g over 1024)
    for (int i=id; i<4*32*32*64; i+=st){
        int e=i&3, lane=(i>>2)&31, np=(i>>7)&15, kc=(i>>11)&31, p=i>>16;
        int ntl = np*2 + (e>>1), slot = e&1;
        int k = kc*8 + 4*slot + (lane&3);
        int C = p*256 + ntl*8 + (lane>>2);
        int u = C>>2, g = C&3; float v = 0.f;
        if (u < H){
            int row = g*H + u;
            if (k >= 8 && k < 56)      v = Wih1[row*DT + k-8];
            else if (k >= 56)          v = Whh1[row*H + k-56];
        }
        g_WAf[i] = t32(v);
    }
    // WB: [p][kc56][np16][lane][e]; A k-order [h1'(200), tiled(48), h2(200)]
    for (int i=id; i<4*56*32*64; i+=st){
        int e=i&3, lane=(i>>2)&31, np=(i>>7)&15, rest=i>>11;
        int kc = rest % 56, p = rest / 56;
        int ntl = np*2 + (e>>1), slot = e&1;
        int k = kc*8 + 4*slot + (lane&3);
        int C = p*256 + ntl*8 + (lane>>2);
        int u = C>>2, g = C&3; float v = 0.f;
        if (u < H){
            int row = g*H + u;
            if (k < 248) v = Wih2[row*248 + k];
            else         v = Whh2[row*H + k-248];
        }
        g_WBf[i] = t32(v);
    }
    // WC: [kc32][np16][lane][e]; A k-order [pad8, x1(48)->W1 col 200.., h2'(200)->W1 col 0..]
    for (int i=id; i<32*32*64; i+=st){
        int e=i&3, lane=(i>>2)&31, np=(i>>7)&15, kc=(i>>11)&31;
        int ntl = np*2 + (e>>1), slot = e&1;
        int k = kc*8 + 4*slot + (lane&3);
        int n = ntl*8 + (lane>>2); float v = 0.f;
        if (n < H){
            if (k >= 8 && k < 56)  v = W1[n*248 + 200 + (k-8)];
            else if (k >= 56)      v = W1[n*248 + (k-56)];
        }
        g_WCf[i] = t32(v);
    }
    // WD: [kc28][np4][lane][e]
    for (int i=id; i<28*8*64; i+=st){
        int e=i&3, lane=(i>>2)&31, np=(i>>7)&3, kc=i>>9;
        int ntl = np*2 + (e>>1), slot = e&1;
        int k = kc*8 + 4*slot + (lane&3);
        int n = ntl*8 + (lane>>2);
        float v = (n < DT && k < H) ? W2[n*H + k] : 0.f;
        g_WDf[i] = t32(v);
    }
    // biases
    for (int i=id; i<1024; i+=st){
        int u=i>>2, g=i&3; float v1=0.f, v2=0.f;
        if (u < H){ v1 = bih1[g*H+u]+bhh1[g*H+u]; v2 = bih2[g*H+u]+bhh2[g*H+u]; }
        g_bb1[i]=v1; g_bb2[i]=v2;
    }
    for (int i=id; i<256; i+=st) g_b1p[i] = (i<H)? b1[i] : 0.f;
    for (int i=id; i<64;  i+=st) g_b2p[i] = (i<DT)? b2[i] : 0.f;
}

// ---------------- panel GEMM: stream W chunks, warp mma ----------------
// NT accumulators (NT even); warp covers ntl range [npBase*2, npBase*2+NT)
template <int NT>
__device__ __forceinline__ void panel_mma(
    const float* __restrict__ Asm, const float* __restrict__ Wg,
    float* __restrict__ Ws, int nkc, int ntlTot,
    float (&acc)[NT][4], int mc, int npBase, int tid, int lane, bool active)
{
#pragma unroll
    for (int j=0; j<NT; j++){ acc[j][0]=0.f; acc[j][1]=0.f; acc[j][2]=0.f; acc[j][3]=0.f; }
    int chunkFl = 4*ntlTot*64;
    int ntp = ntlTot >> 1;
    int nch = nkc >> 2;
    for (int c=0; c<nch; c++){
        __syncthreads();
        for (int i=tid*4; i<chunkFl; i+=NTH*4)
            *(float4*)(Ws+i) = *(const float4*)(Wg + (size_t)c*chunkFl + i);
        __syncthreads();
        if (active){
#pragma unroll
            for (int kcl=0; kcl<4; kcl++){
                int kc = c*4 + kcl;
                float4 av = *(const float4*)(Asm + ((kc*4 + mc)*32 + lane)*4);
                u32 a[4] = {__float_as_uint(av.x), __float_as_uint(av.y),
                            __float_as_uint(av.z), __float_as_uint(av.w)};
#pragma unroll
                for (int jp=0; jp<NT/2; jp++){
                    float4 bv = *(const float4*)(Ws + ((kcl*ntp + npBase + jp)*32 + lane)*4);
                    mma8(acc[2*jp],   a, __float_as_uint(bv.x), __float_as_uint(bv.y));
                    mma8(acc[2*jp+1], a, __float_as_uint(bv.z), __float_as_uint(bv.w));
                }
            }
        }
    }
}

// ---------------- LSTM epilogue (warp tile 16x64, gate-interleaved) -------
__device__ __forceinline__ void epi_lstm(
    float (&acc)[8][4], int p, int nc, int mc,
    const float* __restrict__ bb, float* __restrict__ cG, float* __restrict__ hG,
    float* __restrict__ smDst, int kOff, int row0, int lane)
{
    int rbase = mc*16 + (lane>>2);
    int odd = lane & 1;
#pragma unroll
    for (int j=0; j<8; j++){
        float e0 = __shfl_xor_sync(0xFFFFFFFFu, acc[j][0], 1);
        float e1 = __shfl_xor_sync(0xFFFFFFFFu, acc[j][1], 1);
        float e2 = __shfl_xor_sync(0xFFFFFFFFu, acc[j][2], 1);
        float e3 = __shfl_xor_sync(0xFFFFFFFFu, acc[j][3], 1);
        float zi = odd ? e2 : acc[j][0];
        float zf = odd ? e3 : acc[j][1];
        float zg = odd ? acc[j][2] : e0;
        float zo = odd ? acc[j][3] : e1;
        int r = rbase + (odd ? 8 : 0);
        int u = p*64 + nc*16 + j*2 + ((lane&3)>>1);
        if (u < H){
            float4 b = *(const float4*)(bb + u*4);     // i,f,g,o
            size_t gix = (size_t)u*BB + row0 + r;
            float c = cG[gix];
            float cn = sigf(zf + b.y)*c + sigf(zi + b.x)*tanhff(zg + b.z);
            float hn = sigf(zo + b.w)*tanhff(cn);
            cG[gix] = cn; hG[gix] = hn;
            smDst[aidx(kOff + u, r)] = t32(hn);
        }
    }
}

// ---------------- fused per-timestep kernel -------------------------------
__global__ void __launch_bounds__(NTH, 1)
step_kernel(const float* __restrict__ tact, const float* __restrict__ act,
            float* __restrict__ out, int t, int outFrame, int useFb)
{
    extern __shared__ __align__(16) float sm[];
    float* AsX = sm;                 // 256k x 64m frag = 16384 floats
    float* As2 = sm + 16384;         // 448k x 64m frag = 28672 floats
    float* Ws  = sm + 16384 + 28672; // up to 8192 floats

    int tid = threadIdx.x, w = tid>>5, lane = tid&31;
    int mc = w & 3, nc = w >> 2;     // 4 x 4 warp grid
    int row0 = blockIdx.x * MT;

    // -------- staging (t32-rounded) --------
    for (int i=tid; i<512; i+=NTH) AsX[i] = 0.f;   // kc0 pad = zeros
    if (useFb){
        for (int i=tid; i<DT*MT; i+=NTH){
            int d=i>>6, r=i&63;
            AsX[aidx(8+d, r)] = t32(g_x1fb[(size_t)d*BB + row0 + r]);
        }
    } else {
        for (int i=tid; i<DT*MT; i+=NTH){
            int d=i>>6, r=i&63;
            AsX[aidx(8+d, r)] = t32(tact[((size_t)t*BB + row0 + r)*DT + d]);
        }
    }
    for (int i=tid; i<H*MT; i+=NTH){
        int u=i>>6, r=i&63;
        AsX[aidx(56+u, r)] = t32(g_h1[(size_t)u*BB + row0 + r]);
    }
    for (int i=tid; i<DT*MT; i+=NTH){
        int j=i>>6, r=i&63, jm=j%12;
        size_t row = (size_t)row0 + r;
        float v = (jm<6) ? act[((size_t)(t+1)*BB + row)*DA + jm]
                         : act[row*DA + jm - 6];
        As2[aidx(200+j, r)] = t32(v);
    }
    for (int i=tid; i<H*MT; i+=NTH){
        int u=i>>6, r=i&63;
        As2[aidx(248+u, r)] = t32(g_h2[(size_t)u*BB + row0 + r]);
    }

    float acc[8][4];

    // -------- stage 1: z1 + LSTM1 (h1' -> As2 k=u) --------
    for (int p=0; p<4; p++){
        panel_mma<8>(AsX, g_WAf + (size_t)p*32*32*64, Ws, 32, 32,
                     acc, mc, nc*4, tid, lane, true);
        epi_lstm(acc, p, nc, mc, g_bb1, g_c1, g_h1, As2, 0, row0, lane);
    }
    // -------- stage 2: z2 + LSTM2 (h2' -> AsX k=56+u) --------
    for (int p=0; p<4; p++){
        panel_mma<8>(As2, g_WBf + (size_t)p*56*32*64, Ws, 56, 32,
                     acc, mc, nc*4, tid, lane, true);
        epi_lstm(acc, p, nc, mc, g_bb2, g_c2, g_h2, AsX, 56, row0, lane);
    }
    // -------- stage 3: fc1 + tanh (out3 -> As2 k=n) --------
    {
        panel_mma<8>(AsX, g_WCf, Ws, 32, 32, acc, mc, nc*4, tid, lane, true);
        int r = mc*16 + (lane>>2);
#pragma unroll
        for (int j=0; j<8; j++){
            int nb = (nc*8 + j)*8 + (lane&3)*2;
#pragma unroll
            for (int q=0; q<4; q++){
                int n = nb + (q&1);
                int rr = r + (q>>1)*8;
                if (n < 224)
                    As2[aidx(n, rr)] = t32(tanhff(acc[j][q] + g_b1p[n]));
            }
        }
    }
    // -------- stage 4: fc2 + tanh -> out + feedback --------
    {
        float acc4[8][4];
        panel_mma<8>(As2, g_WDf, Ws, 28, 8, acc4, mc, 0, tid, lane, nc == 0);
        if (nc == 0){
            int r = mc*16 + (lane>>2);
#pragma unroll
            for (int j=0; j<8; j++){
                int nb = j*8 + (lane&3)*2;
#pragma unroll
                for (int q=0; q<4; q++){
                    int n = nb + (q&1);
                    int rr = r + (q>>1)*8;
                    if (n < DT){
                        float v = tanhff(acc4[j][q] + g_b2p[n]);
                        size_t grow = (size_t)row0 + rr;
                        if (outFrame >= 0)
                            out[((size_t)outFrame*BB + grow)*DT + n] = v;
                        g_x1fb[(size_t)n*BB + grow] = v;
                    }
                }
            }
        }
    }
}

// ---------------- host launcher -------------------------------------------
#define SMEM_BYTES ((16384 + 28672 + 8192) * 4)

extern "C" void kernel_launch(void* const* d_in, const int* in_sizes, int n_in,
                              void* d_out, int out_size) {
    const float* tactiles = (const float*)d_in[0];
    const float* actions  = (const float*)d_in[1];
    const float* Wih1 = (const float*)d_in[2];
    const float* Whh1 = (const float*)d_in[3];
    const float* bih1 = (const float*)d_in[4];
    const float* bhh1 = (const float*)d_in[5];
    const float* Wih2 = (const float*)d_in[6];
    const float* Whh2 = (const float*)d_in[7];
    const float* bih2 = (const float*)d_in[8];
    const float* bhh2 = (const float*)d_in[9];
    const float* W1   = (const float*)d_in[10];
    const float* b1   = (const float*)d_in[11];
    const float* W2   = (const float*)d_in[12];
    const float* b2   = (const float*)d_in[13];
    float* out = (float*)d_out;

    cudaFuncSetAttribute(step_kernel,
        cudaFuncAttributeMaxDynamicSharedMemorySize, SMEM_BYTES);

    zero_state<<<2048, 256>>>();
    prep<<<512, 256>>>(Wih1, Whh1, bih1, bhh1,
                       Wih2, Whh2, bih2, bhh2, W1, b1, W2, b2);

    for (int t = 0; t < TT - 1; t++) {
        int useFb    = (t >= CF) ? 1 : 0;
        int outFrame = (t >= CF - 1) ? (t - (CF - 1)) : -1;
        step_kernel<<<NCTA, NTH, SMEM_BYTES>>>(
            tactiles, actions, out, t, outFrame, useFb);
    }
}

// round 13
// speedup vs baseline: 2.5573x; 1.2981x over previous
#include <cuda_runtime.h>
#include <stdint.h>

#define H 200
#define DT 48
#define DA 6
#define TT 20
#define BB 32768
#define CF 10
#define MT 64
#define NCTA 512
#define NTH 512

typedef unsigned int u32;

// ---------------- device globals (no runtime alloc) ----------------
// pair-packed fragment-order weight images
__device__ float g_WAf[4 * 32 * 32 * 64];   // [p][kc32][np16][lane32][e4]
__device__ float g_WBf[4 * 56 * 32 * 64];   // [p][kc56][np16][lane32][e4]
__device__ float g_WCf[32 * 32 * 64];       // [kc32][np16][lane32][e4]
__device__ float g_WDf[28 * 8 * 64];        // [kc28][np4][lane32][e4]
__device__ float g_bb1[1024], g_bb2[1024], g_b1p[256], g_b2p[64];
__device__ float g_h1[(size_t)H * BB];
__device__ float g_h2[(size_t)H * BB];
__device__ float g_c1[(size_t)H * BB];
__device__ float g_c2[(size_t)H * BB];
__device__ float g_x1fb[(size_t)DT * BB];

// ---------------- scalar helpers ----------------
__device__ __forceinline__ float fex2(float x){ float r; asm("ex2.approx.f32 %0,%1;":"=f"(r):"f"(x)); return r; }
__device__ __forceinline__ float frcp(float x){ float r; asm("rcp.approx.f32 %0,%1;":"=f"(r):"f"(x)); return r; }
#define L2E 1.4426950408889634f
__device__ __forceinline__ float sigf(float x){ return frcp(1.f + fex2(-L2E*x)); }
__device__ __forceinline__ float tanhff(float x){ return fmaf(2.f, frcp(1.f + fex2(-2.f*L2E*x)), -1.f); }
__device__ __forceinline__ float t32(float x){ u32 r; asm("cvt.rna.tf32.f32 %0,%1;":"=r"(r):"f"(x)); return __uint_as_float(r); }

// A fragment layout: [kc][mc(4)][lane(32)][slot(4)]
// element (k, m): lane=(m&7)*4+(k&3), slot=((m>>3)&1)+2*((k>>2)&1)
__device__ __forceinline__ int aidx(int k, int m){
    int kc = k >> 3, kk = k & 7, mc = m >> 4, mm = m & 15;
    return ((kc*4 + mc)*32 + (mm&7)*4 + (kk&3))*4 + (mm>>3) + 2*(kk>>2);
}

// tf32 m16n8k8 mma, accumulate in place
__device__ __forceinline__ void mma8(float (&d)[4], const u32 (&a)[4], u32 b0, u32 b1){
    asm volatile("mma.sync.aligned.m16n8k8.row.col.f32.tf32.tf32.f32 "
        "{%0,%1,%2,%3}, {%4,%5,%6,%7}, {%8,%9}, {%0,%1,%2,%3};"
        : "+f"(d[0]), "+f"(d[1]), "+f"(d[2]), "+f"(d[3])
        : "r"(a[0]), "r"(a[1]), "r"(a[2]), "r"(a[3]), "r"(b0), "r"(b1));
}

// 16B async copy global->shared
__device__ __forceinline__ void cpa16(float* s, const float* g){
    asm volatile("cp.async.cg.shared.global [%0], [%1], 16;"
        :: "r"((u32)__cvta_generic_to_shared(s)), "l"(g) : "memory");
}
#define CPC()  asm volatile("cp.async.commit_group;":::"memory")
#define CPW0() asm volatile("cp.async.wait_group 0;":::"memory")

// ---------------- init / prep ----------------
__global__ void zero_state(){
    size_t st = (size_t)gridDim.x*blockDim.x;
    size_t id = (size_t)blockIdx.x*blockDim.x + threadIdx.x;
    for (size_t i=id; i<(size_t)H*BB; i+=st){ g_h1[i]=0.f; g_h2[i]=0.f; g_c1[i]=0.f; g_c2[i]=0.f; }
}

// W pair-packed layout: index = (((kc*(ntlTot/2)+np)*32+lane)*4 + e)
// ntl = np*2 + (e>>1), slot = e&1; element (k,col): k = kc*8+4*slot+(lane&3),
// col = ntl*8 + (lane>>2)
__global__ void prep(
    const float* __restrict__ Wih1, const float* __restrict__ Whh1,
    const float* __restrict__ bih1, const float* __restrict__ bhh1,
    const float* __restrict__ Wih2, const float* __restrict__ Whh2,
    const float* __restrict__ bih2, const float* __restrict__ bhh2,
    const float* __restrict__ W1,   const float* __restrict__ b1,
    const float* __restrict__ W2,   const float* __restrict__ b2)
{
    int st = gridDim.x*blockDim.x, id = blockIdx.x*blockDim.x + threadIdx.x;
    // WA: [p][kc32][np16][lane][e]; cols gate-interleaved (col=u*4+g over 1024)
    for (int i=id; i<4*32*32*64; i+=st){
        int e=i&3, lane=(i>>2)&31, np=(i>>7)&15, kc=(i>>11)&31, p=i>>16;
        int ntl = np*2 + (e>>1), slot = e&1;
        int k = kc*8 + 4*slot + (lane&3);
        int C = p*256 + ntl*8 + (lane>>2);
        int u = C>>2, g = C&3; float v = 0.f;
        if (u < H){
            int row = g*H + u;
            if (k >= 8 && k < 56)      v = Wih1[row*DT + k-8];
            else if (k >= 56)          v = Whh1[row*H + k-56];
        }
        g_WAf[i] = t32(v);
    }
    // WB: [p][kc56][np16][lane][e]; A k-order [h1'(200), tiled(48), h2(200)]
    for (int i=id; i<4*56*32*64; i+=st){
        int e=i&3, lane=(i>>2)&31, np=(i>>7)&15, rest=i>>11;
        int kc = rest % 56, p = rest / 56;
        int ntl = np*2 + (e>>1), slot = e&1;
        int k = kc*8 + 4*slot + (lane&3);
        int C = p*256 + ntl*8 + (lane>>2);
        int u = C>>2, g = C&3; float v = 0.f;
        if (u < H){
            int row = g*H + u;
            if (k < 248) v = Wih2[row*248 + k];
            else         v = Whh2[row*H + k-248];
        }
        g_WBf[i] = t32(v);
    }
    // WC: [kc32][np16][lane][e]; A k-order [pad8, x1(48)->W1 col 200.., h2'(200)->W1 col 0..]
    for (int i=id; i<32*32*64; i+=st){
        int e=i&3, lane=(i>>2)&31, np=(i>>7)&15, kc=(i>>11)&31;
        int ntl = np*2 + (e>>1), slot = e&1;
        int k = kc*8 + 4*slot + (lane&3);
        int n = ntl*8 + (lane>>2); float v = 0.f;
        if (n < H){
            if (k >= 8 && k < 56)  v = W1[n*248 + 200 + (k-8)];
            else if (k >= 56)      v = W1[n*248 + (k-56)];
        }
        g_WCf[i] = t32(v);
    }
    // WD: [kc28][np4][lane][e]
    for (int i=id; i<28*8*64; i+=st){
        int e=i&3, lane=(i>>2)&31, np=(i>>7)&3, kc=i>>9;
        int ntl = np*2 + (e>>1), slot = e&1;
        int k = kc*8 + 4*slot + (lane&3);
        int n = ntl*8 + (lane>>2);
        float v = (n < DT && k < H) ? W2[n*H + k] : 0.f;
        g_WDf[i] = t32(v);
    }
    // biases
    for (int i=id; i<1024; i+=st){
        int u=i>>2, g=i&3; float v1=0.f, v2=0.f;
        if (u < H){ v1 = bih1[g*H+u]+bhh1[g*H+u]; v2 = bih2[g*H+u]+bhh2[g*H+u]; }
        g_bb1[i]=v1; g_bb2[i]=v2;
    }
    for (int i=id; i<256; i+=st) g_b1p[i] = (i<H)? b1[i] : 0.f;
    for (int i=id; i<64;  i+=st) g_b2p[i] = (i<DT)? b2[i] : 0.f;
}

// ---------------- panel GEMM: cp.async double-buffered W stream -----------
// Chunk = 2 k-steps (2 kc). Ws holds 2 buffers of chunkFl floats.
// Per iter: wait chunk c -> barrier -> prefetch c+1 -> compute c.
template <int NT>
__device__ __forceinline__ void panel_mma(
    const float* __restrict__ Asm, const float* __restrict__ Wg,
    float* __restrict__ Ws, int nkc, int ntlTot,
    float (&acc)[NT][4], int mc, int npBase, int tid, int lane, bool active)
{
#pragma unroll
    for (int j=0; j<NT; j++){ acc[j][0]=0.f; acc[j][1]=0.f; acc[j][2]=0.f; acc[j][3]=0.f; }
    int chunkFl = 2*ntlTot*64;       // 2 kc per chunk
    int ntp = ntlTot >> 1;
    int nch = nkc >> 1;

    __syncthreads();                 // prior epilogue writes / Ws reuse safe
    // prologue: chunk 0 -> buf 0
    for (int i=tid*4; i<chunkFl; i+=NTH*4) cpa16(Ws + i, Wg + i);
    CPC();

    for (int c=0; c<nch; c++){
        CPW0();                      // chunk c landed (thread-local)
        __syncthreads();             // CTA-wide visibility + prev compute done
        if (c+1 < nch){
            float* dst = Ws + ((c+1)&1)*chunkFl;
            const float* src = Wg + (size_t)(c+1)*chunkFl;
            for (int i=tid*4; i<chunkFl; i+=NTH*4) cpa16(dst + i, src + i);
            CPC();
        }
        if (active){
            const float* Wb = Ws + (c&1)*chunkFl;
#pragma unroll
            for (int kcl=0; kcl<2; kcl++){
                int kc = c*2 + kcl;
                float4 av = *(const float4*)(Asm + ((kc*4 + mc)*32 + lane)*4);
                u32 a[4] = {__float_as_uint(av.x), __float_as_uint(av.y),
                            __float_as_uint(av.z), __float_as_uint(av.w)};
#pragma unroll
                for (int jp=0; jp<NT/2; jp++){
                    float4 bv = *(const float4*)(Wb + ((kcl*ntp + npBase + jp)*32 + lane)*4);
                    mma8(acc[2*jp],   a, __float_as_uint(bv.x), __float_as_uint(bv.y));
                    mma8(acc[2*jp+1], a, __float_as_uint(bv.z), __float_as_uint(bv.w));
                }
            }
        }
    }
}

// ---------------- LSTM epilogue (warp tile 16x64, gate-interleaved) -------
__device__ __forceinline__ void epi_lstm(
    float (&acc)[8][4], int p, int nc, int mc,
    const float* __restrict__ bb, float* __restrict__ cG, float* __restrict__ hG,
    float* __restrict__ smDst, int kOff, int row0, int lane)
{
    int rbase = mc*16 + (lane>>2);
    int odd = lane & 1;
#pragma unroll
    for (int j=0; j<8; j++){
        float e0 = __shfl_xor_sync(0xFFFFFFFFu, acc[j][0], 1);
        float e1 = __shfl_xor_sync(0xFFFFFFFFu, acc[j][1], 1);
        float e2 = __shfl_xor_sync(0xFFFFFFFFu, acc[j][2], 1);
        float e3 = __shfl_xor_sync(0xFFFFFFFFu, acc[j][3], 1);
        float zi = odd ? e2 : acc[j][0];
        float zf = odd ? e3 : acc[j][1];
        float zg = odd ? acc[j][2] : e0;
        float zo = odd ? acc[j][3] : e1;
        int r = rbase + (odd ? 8 : 0);
        int u = p*64 + nc*16 + j*2 + ((lane&3)>>1);
        if (u < H){
            float4 b = *(const float4*)(bb + u*4);     // i,f,g,o
            size_t gix = (size_t)u*BB + row0 + r;
            float c = cG[gix];
            float cn = sigf(zf + b.y)*c + sigf(zi + b.x)*tanhff(zg + b.z);
            float hn = sigf(zo + b.w)*tanhff(cn);
            cG[gix] = cn; hG[gix] = hn;
            smDst[aidx(kOff + u, r)] = t32(hn);
        }
    }
}

// ---------------- fused per-timestep kernel -------------------------------
__global__ void __launch_bounds__(NTH, 1)
step_kernel(const float* __restrict__ tact, const float* __restrict__ act,
            float* __restrict__ out, int t, int outFrame, int useFb)
{
    extern __shared__ __align__(16) float sm[];
    float* AsX = sm;                 // 256k x 64m frag = 16384 floats
    float* As2 = sm + 16384;         // 448k x 64m frag = 28672 floats
    float* Ws  = sm + 16384 + 28672; // 2 x 4096 floats (double buffer)

    int tid = threadIdx.x, w = tid>>5, lane = tid&31;
    int mc = w & 3, nc = w >> 2;     // 4 x 4 warp grid
    int row0 = blockIdx.x * MT;

    // -------- staging (t32-rounded) --------
    for (int i=tid; i<512; i+=NTH) AsX[i] = 0.f;   // kc0 pad = zeros
    if (useFb){
        for (int i=tid; i<DT*MT; i+=NTH){
            int d=i>>6, r=i&63;
            AsX[aidx(8+d, r)] = t32(g_x1fb[(size_t)d*BB + row0 + r]);
        }
    } else {
        for (int i=tid; i<DT*MT; i+=NTH){
            int d=i>>6, r=i&63;
            AsX[aidx(8+d, r)] = t32(tact[((size_t)t*BB + row0 + r)*DT + d]);
        }
    }
    for (int i=tid; i<H*MT; i+=NTH){
        int u=i>>6, r=i&63;
        AsX[aidx(56+u, r)] = t32(g_h1[(size_t)u*BB + row0 + r]);
    }
    for (int i=tid; i<DT*MT; i+=NTH){
        int j=i>>6, r=i&63, jm=j%12;
        size_t row = (size_t)row0 + r;
        float v = (jm<6) ? act[((size_t)(t+1)*BB + row)*DA + jm]
                         : act[row*DA + jm - 6];
        As2[aidx(200+j, r)] = t32(v);
    }
    for (int i=tid; i<H*MT; i+=NTH){
        int u=i>>6, r=i&63;
        As2[aidx(248+u, r)] = t32(g_h2[(size_t)u*BB + row0 + r]);
    }

    float acc[8][4];

    // -------- stage 1: z1 + LSTM1 (h1' -> As2 k=u) --------
    for (int p=0; p<4; p++){
        panel_mma<8>(AsX, g_WAf + (size_t)p*32*32*64, Ws, 32, 32,
                     acc, mc, nc*4, tid, lane, true);
        epi_lstm(acc, p, nc, mc, g_bb1, g_c1, g_h1, As2, 0, row0, lane);
    }
    // -------- stage 2: z2 + LSTM2 (h2' -> AsX k=56+u) --------
    for (int p=0; p<4; p++){
        panel_mma<8>(As2, g_WBf + (size_t)p*56*32*64, Ws, 56, 32,
                     acc, mc, nc*4, tid, lane, true);
        epi_lstm(acc, p, nc, mc, g_bb2, g_c2, g_h2, AsX, 56, row0, lane);
    }
    // -------- stage 3: fc1 + tanh (out3 -> As2 k=n) --------
    {
        panel_mma<8>(AsX, g_WCf, Ws, 32, 32, acc, mc, nc*4, tid, lane, true);
        int r = mc*16 + (lane>>2);
#pragma unroll
        for (int j=0; j<8; j++){
            int nb = (nc*8 + j)*8 + (lane&3)*2;
#pragma unroll
            for (int q=0; q<4; q++){
                int n = nb + (q&1);
                int rr = r + (q>>1)*8;
                if (n < 224)
                    As2[aidx(n, rr)] = t32(tanhff(acc[j][q] + g_b1p[n]));
            }
        }
    }
    // -------- stage 4: fc2 + tanh -> out + feedback --------
    {
        float acc4[8][4];
        panel_mma<8>(As2, g_WDf, Ws, 28, 8, acc4, mc, 0, tid, lane, nc == 0);
        if (nc == 0){
            int r = mc*16 + (lane>>2);
#pragma unroll
            for (int j=0; j<8; j++){
                int nb = j*8 + (lane&3)*2;
#pragma unroll
                for (int q=0; q<4; q++){
                    int n = nb + (q&1);
                    int rr = r + (q>>1)*8;
                    if (n < DT){
                        float v = tanhff(acc4[j][q] + g_b2p[n]);
                        size_t grow = (size_t)row0 + rr;
                        if (outFrame >= 0)
                            out[((size_t)outFrame*BB + grow)*DT + n] = v;
                        g_x1fb[(size_t)n*BB + grow] = v;
                    }
                }
            }
        }
    }
}

// ---------------- host launcher -------------------------------------------
#define SMEM_BYTES ((16384 + 28672 + 8192) * 4)

extern "C" void kernel_launch(void* const* d_in, const int* in_sizes, int n_in,
                              void* d_out, int out_size) {
    const float* tactiles = (const float*)d_in[0];
    const float* actions  = (const float*)d_in[1];
    const float* Wih1 = (const float*)d_in[2];
    const float* Whh1 = (const float*)d_in[3];
    const float* bih1 = (const float*)d_in[4];
    const float* bhh1 = (const float*)d_in[5];
    const float* Wih2 = (const float*)d_in[6];
    const float* Whh2 = (const float*)d_in[7];
    const float* bih2 = (const float*)d_in[8];
    const float* bhh2 = (const float*)d_in[9];
    const float* W1   = (const float*)d_in[10];
    const float* b1   = (const float*)d_in[11];
    const float* W2   = (const float*)d_in[12];
    const float* b2   = (const float*)d_in[13];
    float* out = (float*)d_out;

    cudaFuncSetAttribute(step_kernel,
        cudaFuncAttributeMaxDynamicSharedMemorySize, SMEM_BYTES);

    zero_state<<<2048, 256>>>();
    prep<<<512, 256>>>(Wih1, Whh1, bih1, bhh1,
                       Wih2, Whh2, bih2, bhh2, W1, b1, W2, b2);

    for (int t = 0; t < TT - 1; t++) {
        int useFb    = (t >= CF) ? 1 : 0;
        int outFrame = (t >= CF - 1) ? (t - (CF - 1)) : -1;
        step_kernel<<<NCTA, NTH, SMEM_BYTES>>>(
            tactiles, actions, out, t, outFrame, useFb);
    }
}

// round 14
// speedup vs baseline: 2.6609x; 1.0405x over previous
#include <cuda_runtime.h>
#include <stdint.h>

#define H 200
#define DT 48
#define DA 6
#define TT 20
#define BB 32768
#define CF 10
#define MT 64
#define NCTA 512
#define NTH 512

typedef unsigned int u32;

// ---------------- device globals (no runtime alloc) ----------------
// pair-packed fragment-order weight images
__device__ float g_WAf[4 * 32 * 32 * 64];   // [p][kc32][np16][lane32][e4]
__device__ float g_WBf[4 * 56 * 32 * 64];   // [p][kc56][np16][lane32][e4]
__device__ float g_WCf[32 * 32 * 64];       // [kc32][np16][lane32][e4]
__device__ float g_WDf[28 * 8 * 64];        // [kc28][np4][lane32][e4]
__device__ float g_bb1[1024], g_bb2[1024], g_b1p[256], g_b2p[64];
__device__ float g_h1[(size_t)H * BB];
__device__ float g_h2[(size_t)H * BB];
__device__ float g_c1[(size_t)H * BB];
__device__ float g_c2[(size_t)H * BB];
__device__ float g_x1fb[(size_t)DT * BB];

// ---------------- scalar helpers ----------------
__device__ __forceinline__ float fex2(float x){ float r; asm("ex2.approx.f32 %0,%1;":"=f"(r):"f"(x)); return r; }
__device__ __forceinline__ float frcp(float x){ float r; asm("rcp.approx.f32 %0,%1;":"=f"(r):"f"(x)); return r; }
#define L2E 1.4426950408889634f
__device__ __forceinline__ float sigf(float x){ return frcp(1.f + fex2(-L2E*x)); }
__device__ __forceinline__ float tanhff(float x){ return fmaf(2.f, frcp(1.f + fex2(-2.f*L2E*x)), -1.f); }
__device__ __forceinline__ float t32(float x){ u32 r; asm("cvt.rna.tf32.f32 %0,%1;":"=r"(r):"f"(x)); return __uint_as_float(r); }

// A fragment layout: [kc][mfrag(4)][lane(32)][slot(4)]
// element (k, m): lane=(m&7)*4+(k&3), slot=((m>>3)&1)+2*((k>>2)&1)
__device__ __forceinline__ int aidx(int k, int m){
    int kc = k >> 3, kk = k & 7, mf = m >> 4, mm = m & 15;
    return ((kc*4 + mf)*32 + (mm&7)*4 + (kk&3))*4 + (mm>>3) + 2*(kk>>2);
}

// tf32 m16n8k8 mma, accumulate in place
__device__ __forceinline__ void mma8(float (&d)[4], const u32 (&a)[4], u32 b0, u32 b1){
    asm volatile("mma.sync.aligned.m16n8k8.row.col.f32.tf32.tf32.f32 "
        "{%0,%1,%2,%3}, {%4,%5,%6,%7}, {%8,%9}, {%0,%1,%2,%3};"
        : "+f"(d[0]), "+f"(d[1]), "+f"(d[2]), "+f"(d[3])
        : "r"(a[0]), "r"(a[1]), "r"(a[2]), "r"(a[3]), "r"(b0), "r"(b1));
}

// 16B async copy global->shared
__device__ __forceinline__ void cpa16(float* s, const float* g){
    asm volatile("cp.async.cg.shared.global [%0], [%1], 16;"
        :: "r"((u32)__cvta_generic_to_shared(s)), "l"(g) : "memory");
}
#define CPC()  asm volatile("cp.async.commit_group;":::"memory")
#define CPW0() asm volatile("cp.async.wait_group 0;":::"memory")
#define CPW1() asm volatile("cp.async.wait_group 1;":::"memory")

// ---------------- init / prep ----------------
__global__ void zero_state(){
    size_t st = (size_t)gridDim.x*blockDim.x;
    size_t id = (size_t)blockIdx.x*blockDim.x + threadIdx.x;
    for (size_t i=id; i<(size_t)H*BB; i+=st){ g_h1[i]=0.f; g_h2[i]=0.f; g_c1[i]=0.f; g_c2[i]=0.f; }
}

// W pair-packed layout: index = (((kc*(ntlTot/2)+np)*32+lane)*4 + e)
// ntl = np*2 + (e>>1), slot = e&1; element (k,col): k = kc*8+4*slot+(lane&3),
// col = ntl*8 + (lane>>2)
__global__ void prep(
    const float* __restrict__ Wih1, const float* __restrict__ Whh1,
    const float* __restrict__ bih1, const float* __restrict__ bhh1,
    const float* __restrict__ Wih2, const float* __restrict__ Whh2,
    const float* __restrict__ bih2, const float* __restrict__ bhh2,
    const float* __restrict__ W1,   const float* __restrict__ b1,
    const float* __restrict__ W2,   const float* __restrict__ b2)
{
    int st = gridDim.x*blockDim.x, id = blockIdx.x*blockDim.x + threadIdx.x;
    // WA: [p][kc32][np16][lane][e]; cols gate-interleaved (col=u*4+g over 1024)
    for (int i=id; i<4*32*32*64; i+=st){
        int e=i&3, lane=(i>>2)&31, np=(i>>7)&15, kc=(i>>11)&31, p=i>>16;
        int ntl = np*2 + (e>>1), slot = e&1;
        int k = kc*8 + 4*slot + (lane&3);
        int C = p*256 + ntl*8 + (lane>>2);
        int u = C>>2, g = C&3; float v = 0.f;
        if (u < H){
            int row = g*H + u;
            if (k >= 8 && k < 56)      v = Wih1[row*DT + k-8];
            else if (k >= 56)          v = Whh1[row*H + k-56];
        }
        g_WAf[i] = t32(v);
    }
    // WB: [p][kc56][np16][lane][e]; A k-order [h1'(200), tiled(48), h2(200)]
    for (int i=id; i<4*56*32*64; i+=st){
        int e=i&3, lane=(i>>2)&31, np=(i>>7)&15, rest=i>>11;
        int kc = rest % 56, p = rest / 56;
        int ntl = np*2 + (e>>1), slot = e&1;
        int k = kc*8 + 4*slot + (lane&3);
        int C = p*256 + ntl*8 + (lane>>2);
        int u = C>>2, g = C&3; float v = 0.f;
        if (u < H){
            int row = g*H + u;
            if (k < 248) v = Wih2[row*248 + k];
            else         v = Whh2[row*H + k-248];
        }
        g_WBf[i] = t32(v);
    }
    // WC: [kc32][np16][lane][e]; A k-order [pad8, x1(48)->W1 col 200.., h2'(200)->W1 col 0..]
    for (int i=id; i<32*32*64; i+=st){
        int e=i&3, lane=(i>>2)&31, np=(i>>7)&15, kc=(i>>11)&31;
        int ntl = np*2 + (e>>1), slot = e&1;
        int k = kc*8 + 4*slot + (lane&3);
        int n = ntl*8 + (lane>>2); float v = 0.f;
        if (n < H){
            if (k >= 8 && k < 56)  v = W1[n*248 + 200 + (k-8)];
            else if (k >= 56)      v = W1[n*248 + (k-56)];
        }
        g_WCf[i] = t32(v);
    }
    // WD: [kc28][np4][lane][e]
    for (int i=id; i<28*8*64; i+=st){
        int e=i&3, lane=(i>>2)&31, np=(i>>7)&3, kc=i>>9;
        int ntl = np*2 + (e>>1), slot = e&1;
        int k = kc*8 + 4*slot + (lane&3);
        int n = ntl*8 + (lane>>2);
        float v = (n < DT && k < H) ? W2[n*H + k] : 0.f;
        g_WDf[i] = t32(v);
    }
    // biases
    for (int i=id; i<1024; i+=st){
        int u=i>>2, g=i&3; float v1=0.f, v2=0.f;
        if (u < H){ v1 = bih1[g*H+u]+bhh1[g*H+u]; v2 = bih2[g*H+u]+bhh2[g*H+u]; }
        g_bb1[i]=v1; g_bb2[i]=v2;
    }
    for (int i=id; i<256; i+=st) g_b1p[i] = (i<H)? b1[i] : 0.f;
    for (int i=id; i<64;  i+=st) g_b2p[i] = (i<DT)? b2[i] : 0.f;
}

// ---------------- panel GEMM: 3-deep cp.async pipeline, 32x32 warp tile ---
// Warp grid 2(mc) x 8(nc). Per warp per kc: 2 A LDS + 2 B LDS + 8 MMA.
// acc[fm][j][e]: fm = m-frag (rows mc*32+fm*16+..), j = ntl (8 cols each).
template <int NKC, int NTLTOT>
__device__ __forceinline__ void panel_mma(
    const float* __restrict__ Asm, const float* __restrict__ Wg,
    float* __restrict__ Ws, float (&acc)[2][4][4],
    int mc, int npBase, int tid, int lane, bool active)
{
    constexpr int NTP = NTLTOT >> 1;        // np per kc row of W image
    constexpr int CHF = 2*NTLTOT*64;        // floats per chunk (2 kc)
    constexpr int NCH = NKC >> 1;
#pragma unroll
    for (int f=0; f<2; f++)
#pragma unroll
        for (int j=0; j<4; j++)
#pragma unroll
            for (int e=0; e<4; e++) acc[f][j][e] = 0.f;

    __syncthreads();   // prior epilogue writes done; Ws free
    // prologue: chunks 0,1
    for (int i=tid*4; i<CHF; i+=NTH*4) cpa16(Ws + i, Wg + i);
    CPC();
    for (int i=tid*4; i<CHF; i+=NTH*4) cpa16(Ws + CHF + i, Wg + CHF + i);
    CPC();

    const float* Aw = Asm + (mc*64 + lane)*4;       // mc*2 frags * 32 lanes
    const int woff = (npBase*32 + lane)*4;

    for (int c=0; c<NCH; c++){
        if (c+1 < NCH) CPW1(); else CPW0();   // chunk c landed
        __syncthreads();                      // CTA-visible; buf (c+2)%3 free
        if (c+2 < NCH){
            float* dst = Ws + ((c+2)%3)*CHF;
            const float* src = Wg + (size_t)(c+2)*CHF;
            for (int i=tid*4; i<CHF; i+=NTH*4) cpa16(dst + i, src + i);
            CPC();
        }
        if (active){
            const float* Wb = Ws + (c%3)*CHF + woff;
            const float* Ar = Aw + c*1024;    // 2 kc * 512 floats
#pragma unroll
            for (int kcl=0; kcl<2; kcl++){
                float4 a0v = *(const float4*)(Ar + kcl*512);
                float4 a1v = *(const float4*)(Ar + kcl*512 + 128);
                u32 a0[4] = {__float_as_uint(a0v.x), __float_as_uint(a0v.y),
                             __float_as_uint(a0v.z), __float_as_uint(a0v.w)};
                u32 a1[4] = {__float_as_uint(a1v.x), __float_as_uint(a1v.y),
                             __float_as_uint(a1v.z), __float_as_uint(a1v.w)};
                float4 b0 = *(const float4*)(Wb + kcl*NTP*128);
                float4 b1 = *(const float4*)(Wb + kcl*NTP*128 + 128);
                mma8(acc[0][0], a0, __float_as_uint(b0.x), __float_as_uint(b0.y));
                mma8(acc[0][1], a0, __float_as_uint(b0.z), __float_as_uint(b0.w));
                mma8(acc[0][2], a0, __float_as_uint(b1.x), __float_as_uint(b1.y));
                mma8(acc[0][3], a0, __float_as_uint(b1.z), __float_as_uint(b1.w));
                mma8(acc[1][0], a1, __float_as_uint(b0.x), __float_as_uint(b0.y));
                mma8(acc[1][1], a1, __float_as_uint(b0.z), __float_as_uint(b0.w));
                mma8(acc[1][2], a1, __float_as_uint(b1.x), __float_as_uint(b1.y));
                mma8(acc[1][3], a1, __float_as_uint(b1.z), __float_as_uint(b1.w));
            }
        }
    }
}

// ---------------- LSTM epilogue (warp tile 32x32, gate-interleaved) -------
__device__ __forceinline__ void epi_lstm(
    float (&acc)[2][4][4], int p, int nc, int mc,
    const float* __restrict__ bb, float* __restrict__ cG, float* __restrict__ hG,
    float* __restrict__ smDst, int kOff, int row0, int lane)
{
    int odd = lane & 1;
#pragma unroll
    for (int fm=0; fm<2; fm++){
        int rbase = mc*32 + fm*16 + (lane>>2);
#pragma unroll
        for (int j=0; j<4; j++){
            float e0 = __shfl_xor_sync(0xFFFFFFFFu, acc[fm][j][0], 1);
            float e1 = __shfl_xor_sync(0xFFFFFFFFu, acc[fm][j][1], 1);
            float e2 = __shfl_xor_sync(0xFFFFFFFFu, acc[fm][j][2], 1);
            float e3 = __shfl_xor_sync(0xFFFFFFFFu, acc[fm][j][3], 1);
            float zi = odd ? e2 : acc[fm][j][0];
            float zf = odd ? e3 : acc[fm][j][1];
            float zg = odd ? acc[fm][j][2] : e0;
            float zo = odd ? acc[fm][j][3] : e1;
            int r = rbase + (odd ? 8 : 0);
            int u = p*64 + nc*8 + j*2 + ((lane&3)>>1);
            if (u < H){
                float4 b = *(const float4*)(bb + u*4);     // i,f,g,o
                size_t gix = (size_t)u*BB + row0 + r;
                float c = cG[gix];
                float cn = sigf(zf + b.y)*c + sigf(zi + b.x)*tanhff(zg + b.z);
                float hn = sigf(zo + b.w)*tanhff(cn);
                cG[gix] = cn; hG[gix] = hn;
                smDst[aidx(kOff + u, r)] = t32(hn);
            }
        }
    }
}

// ---------------- fused per-timestep kernel -------------------------------
__global__ void __launch_bounds__(NTH, 1)
step_kernel(const float* __restrict__ tact, const float* __restrict__ act,
            float* __restrict__ out, int t, int outFrame, int useFb)
{
    extern __shared__ __align__(16) float sm[];
    float* AsX = sm;                 // 256k x 64m frag = 16384 floats
    float* As2 = sm + 16384;         // 448k x 64m frag = 28672 floats
    float* Ws  = sm + 16384 + 28672; // 3 x 4096 floats (triple buffer)

    int tid = threadIdx.x, w = tid>>5, lane = tid&31;
    int mc = w & 1, nc = w >> 1;     // 2 x 8 warp grid
    int row0 = blockIdx.x * MT;

    // -------- staging (t32-rounded) --------
    for (int i=tid; i<512; i+=NTH) AsX[i] = 0.f;   // kc0 pad = zeros
    if (useFb){
        for (int i=tid; i<DT*MT; i+=NTH){
            int d=i>>6, r=i&63;
            AsX[aidx(8+d, r)] = t32(g_x1fb[(size_t)d*BB + row0 + r]);
        }
    } else {
        for (int i=tid; i<DT*MT; i+=NTH){
            int d=i>>6, r=i&63;
            AsX[aidx(8+d, r)] = t32(tact[((size_t)t*BB + row0 + r)*DT + d]);
        }
    }
    for (int i=tid; i<H*MT; i+=NTH){
        int u=i>>6, r=i&63;
        AsX[aidx(56+u, r)] = t32(g_h1[(size_t)u*BB + row0 + r]);
    }
    for (int i=tid; i<DT*MT; i+=NTH){
        int j=i>>6, r=i&63, jm=j%12;
        size_t row = (size_t)row0 + r;
        float v = (jm<6) ? act[((size_t)(t+1)*BB + row)*DA + jm]
                         : act[row*DA + jm - 6];
        As2[aidx(200+j, r)] = t32(v);
    }
    for (int i=tid; i<H*MT; i+=NTH){
        int u=i>>6, r=i&63;
        As2[aidx(248+u, r)] = t32(g_h2[(size_t)u*BB + row0 + r]);
    }

    float acc[2][4][4];

    // -------- stage 1: z1 + LSTM1 (h1' -> As2 k=u) --------
    for (int p=0; p<4; p++){
        panel_mma<32,32>(AsX, g_WAf + (size_t)p*32*32*64, Ws,
                         acc, mc, nc*2, tid, lane, true);
        epi_lstm(acc, p, nc, mc, g_bb1, g_c1, g_h1, As2, 0, row0, lane);
    }
    // -------- stage 2: z2 + LSTM2 (h2' -> AsX k=56+u) --------
    for (int p=0; p<4; p++){
        panel_mma<56,32>(As2, g_WBf + (size_t)p*56*32*64, Ws,
                         acc, mc, nc*2, tid, lane, true);
        epi_lstm(acc, p, nc, mc, g_bb2, g_c2, g_h2, AsX, 56, row0, lane);
    }
    // -------- stage 3: fc1 + tanh (out3 -> As2 k=n) --------
    {
        panel_mma<32,32>(AsX, g_WCf, Ws, acc, mc, nc*2, tid, lane, true);
#pragma unroll
        for (int fm=0; fm<2; fm++){
            int rb = mc*32 + fm*16 + (lane>>2);
#pragma unroll
            for (int j=0; j<4; j++){
                int nb = nc*32 + j*8 + (lane&3)*2;
#pragma unroll
                for (int q=0; q<4; q++){
                    int n = nb + (q&1);
                    int rr = rb + (q>>1)*8;
                    if (n < 224)
                        As2[aidx(n, rr)] = t32(tanhff(acc[fm][j][q] + g_b1p[n]));
                }
            }
        }
    }
    // -------- stage 4: fc2 + tanh -> out + feedback --------
    {
        float acc4[2][4][4];
        panel_mma<28,8>(As2, g_WDf, Ws, acc4, mc, nc*2, tid, lane, nc < 2);
        if (nc < 2){
#pragma unroll
            for (int fm=0; fm<2; fm++){
                int rb = mc*32 + fm*16 + (lane>>2);
#pragma unroll
                for (int j=0; j<4; j++){
                    int nb = nc*32 + j*8 + (lane&3)*2;
#pragma unroll
                    for (int q=0; q<4; q++){
                        int n = nb + (q&1);
                        int rr = rb + (q>>1)*8;
                        if (n < DT){
                            float v = tanhff(acc4[fm][j][q] + g_b2p[n]);
                            size_t grow = (size_t)row0 + rr;
                            if (outFrame >= 0)
                                out[((size_t)outFrame*BB + grow)*DT + n] = v;
                            g_x1fb[(size_t)n*BB + grow] = v;
                        }
                    }
                }
            }
        }
    }
}

// ---------------- host launcher -------------------------------------------
#define SMEM_BYTES ((16384 + 28672 + 12288) * 4)

extern "C" void kernel_launch(void* const* d_in, const int* in_sizes, int n_in,
                              void* d_out, int out_size) {
    const float* tactiles = (const float*)d_in[0];
    const float* actions  = (const float*)d_in[1];
    const float* Wih1 = (const float*)d_in[2];
    const float* Whh1 = (const float*)d_in[3];
    const float* bih1 = (const float*)d_in[4];
    const float* bhh1 = (const float*)d_in[5];
    const float* Wih2 = (const float*)d_in[6];
    const float* Whh2 = (const float*)d_in[7];
    const float* bih2 = (const float*)d_in[8];
    const float* bhh2 = (const float*)d_in[9];
    const float* W1   = (const float*)d_in[10];
    const float* b1   = (const float*)d_in[11];
    const float* W2   = (const float*)d_in[12];
    const float* b2   = (const float*)d_in[13];
    float* out = (float*)d_out;

    cudaFuncSetAttribute(step_kernel,
        cudaFuncAttributeMaxDynamicSharedMemorySize, SMEM_BYTES);

    zero_state<<<2048, 256>>>();
    prep<<<512, 256>>>(Wih1, Whh1, bih1, bhh1,
                       Wih2, Whh2, bih2, bhh2, W1, b1, W2, b2);

    for (int t = 0; t < TT - 1; t++) {
        int useFb    = (t >= CF) ? 1 : 0;
        int outFrame = (t >= CF - 1) ? (t - (CF - 1)) : -1;
        step_kernel<<<NCTA, NTH, SMEM_BYTES>>>(
            tactiles, actions, out, t, outFrame, useFb);
    }
}

// round 15
// speedup vs baseline: 3.8301x; 1.4394x over previous
#include <cuda_runtime.h>
#include <stdint.h>

#define H 200
#define DT 48
#define DA 6
#define TT 20
#define BB 32768
#define CF 10
#define MT 64
#define NCTA 512
#define NTH 512

typedef unsigned int u32;

// ---------------- device globals (no runtime alloc) ----------------
// pair-packed fragment-order weight images
__device__ float g_WAf[4 * 32 * 32 * 64];   // [p][kc32][np16][lane32][e4]
__device__ float g_WBf[4 * 56 * 32 * 64];   // [p][kc56][np16][lane32][e4]
__device__ float g_WCf[32 * 32 * 64];       // [kc32][np16][lane32][e4]
__device__ float g_WDf[28 * 8 * 64];        // [kc28][np4][lane32][e4]
__device__ float g_bb1[1024], g_bb2[1024], g_b1p[256], g_b2p[64];
__device__ float g_h1[(size_t)H * BB];
__device__ float g_h2[(size_t)H * BB];
__device__ float g_c1[(size_t)H * BB];
__device__ float g_c2[(size_t)H * BB];
__device__ float g_x1fb[(size_t)DT * BB];

// ---------------- scalar helpers ----------------
__device__ __forceinline__ float fex2(float x){ float r; asm("ex2.approx.f32 %0,%1;":"=f"(r):"f"(x)); return r; }
__device__ __forceinline__ float frcp(float x){ float r; asm("rcp.approx.f32 %0,%1;":"=f"(r):"f"(x)); return r; }
#define L2E 1.4426950408889634f
__device__ __forceinline__ float sigf(float x){ return frcp(1.f + fex2(-L2E*x)); }
__device__ __forceinline__ float tanhff(float x){ return fmaf(2.f, frcp(1.f + fex2(-2.f*L2E*x)), -1.f); }
__device__ __forceinline__ float t32(float x){ u32 r; asm("cvt.rna.tf32.f32 %0,%1;":"=r"(r):"f"(x)); return __uint_as_float(r); }

// A fragment layout: [kc][mfrag(4)][lane(32)][slot(4)]
// element (k, m): lane=(m&7)*4+(k&3), slot=((m>>3)&1)+2*((k>>2)&1)
__device__ __forceinline__ int aidx(int k, int m){
    int kc = k >> 3, kk = k & 7, mf = m >> 4, mm = m & 15;
    return ((kc*4 + mf)*32 + (mm&7)*4 + (kk&3))*4 + (mm>>3) + 2*(kk>>2);
}

// tf32 m16n8k8 mma, accumulate in place
__device__ __forceinline__ void mma8(float (&d)[4], const u32 (&a)[4], u32 b0, u32 b1){
    asm volatile("mma.sync.aligned.m16n8k8.row.col.f32.tf32.tf32.f32 "
        "{%0,%1,%2,%3}, {%4,%5,%6,%7}, {%8,%9}, {%0,%1,%2,%3};"
        : "+f"(d[0]), "+f"(d[1]), "+f"(d[2]), "+f"(d[3])
        : "r"(a[0]), "r"(a[1]), "r"(a[2]), "r"(a[3]), "r"(b0), "r"(b1));
}

// ---------------- init / prep ----------------
__global__ void zero_state(){
    size_t st = (size_t)gridDim.x*blockDim.x;
    size_t id = (size_t)blockIdx.x*blockDim.x + threadIdx.x;
    for (size_t i=id; i<(size_t)H*BB; i+=st){ g_h1[i]=0.f; g_h2[i]=0.f; g_c1[i]=0.f; g_c2[i]=0.f; }
}

// W pair-packed layout: index = (((kc*(ntlTot/2)+np)*32+lane)*4 + e)
// ntl = np*2 + (e>>1), slot = e&1; element (k,col): k = kc*8+4*slot+(lane&3),
// col = ntl*8 + (lane>>2)
__global__ void prep(
    const float* __restrict__ Wih1, const float* __restrict__ Whh1,
    const float* __restrict__ bih1, const float* __restrict__ bhh1,
    const float* __restrict__ Wih2, const float* __restrict__ Whh2,
    const float* __restrict__ bih2, const float* __restrict__ bhh2,
    const float* __restrict__ W1,   const float* __restrict__ b1,
    const float* __restrict__ W2,   const float* __restrict__ b2)
{
    int st = gridDim.x*blockDim.x, id = blockIdx.x*blockDim.x + threadIdx.x;
    // WA: [p][kc32][np16][lane][e]; cols gate-interleaved (col=u*4+g over 1024)
    for (int i=id; i<4*32*32*64; i+=st){
        int e=i&3, lane=(i>>2)&31, np=(i>>7)&15, kc=(i>>11)&31, p=i>>16;
        int ntl = np*2 + (e>>1), slot = e&1;
        int k = kc*8 + 4*slot + (lane&3);
        int C = p*256 + ntl*8 + (lane>>2);
        int u = C>>2, g = C&3; float v = 0.f;
        if (u < H){
            int row = g*H + u;
            if (k >= 8 && k < 56)      v = Wih1[row*DT + k-8];
            else if (k >= 56)          v = Whh1[row*H + k-56];
        }
        g_WAf[i] = t32(v);
    }
    // WB: [p][kc56][np16][lane][e]; A k-order [h1'(200), tiled(48), h2(200)]
    for (int i=id; i<4*56*32*64; i+=st){
        int e=i&3, lane=(i>>2)&31, np=(i>>7)&15, rest=i>>11;
        int kc = rest % 56, p = rest / 56;
        int ntl = np*2 + (e>>1), slot = e&1;
        int k = kc*8 + 4*slot + (lane&3);
        int C = p*256 + ntl*8 + (lane>>2);
        int u = C>>2, g = C&3; float v = 0.f;
        if (u < H){
            int row = g*H + u;
            if (k < 248) v = Wih2[row*248 + k];
            else         v = Whh2[row*H + k-248];
        }
        g_WBf[i] = t32(v);
    }
    // WC: [kc32][np16][lane][e]; A k-order [pad8, x1(48)->W1 col 200.., h2'(200)->W1 col 0..]
    for (int i=id; i<32*32*64; i+=st){
        int e=i&3, lane=(i>>2)&31, np=(i>>7)&15, kc=(i>>11)&31;
        int ntl = np*2 + (e>>1), slot = e&1;
        int k = kc*8 + 4*slot + (lane&3);
        int n = ntl*8 + (lane>>2); float v = 0.f;
        if (n < H){
            if (k >= 8 && k < 56)  v = W1[n*248 + 200 + (k-8)];
            else if (k >= 56)      v = W1[n*248 + (k-56)];
        }
        g_WCf[i] = t32(v);
    }
    // WD: [kc28][np4][lane][e]
    for (int i=id; i<28*8*64; i+=st){
        int e=i&3, lane=(i>>2)&31, np=(i>>7)&3, kc=i>>9;
        int ntl = np*2 + (e>>1), slot = e&1;
        int k = kc*8 + 4*slot + (lane&3);
        int n = ntl*8 + (lane>>2);
        float v = (n < DT && k < H) ? W2[n*H + k] : 0.f;
        g_WDf[i] = t32(v);
    }
    // biases
    for (int i=id; i<1024; i+=st){
        int u=i>>2, g=i&3; float v1=0.f, v2=0.f;
        if (u < H){ v1 = bih1[g*H+u]+bhh1[g*H+u]; v2 = bih2[g*H+u]+bhh2[g*H+u]; }
        g_bb1[i]=v1; g_bb2[i]=v2;
    }
    for (int i=id; i<256; i+=st) g_b1p[i] = (i<H)? b1[i] : 0.f;
    for (int i=id; i<64;  i+=st) g_b2p[i] = (i<DT)? b2[i] : 0.f;
}

// ---------------- panel GEMM: B direct from L2, register-pipelined --------
// Warp grid 2(mc) x 8(nc); warp tile 32x32. Per kc: 2 A LDS.128 + 2 B LDG.128
// (prefetched one kc ahead) + 8 MMA. NO mainloop barriers.
template <int NKC, int NTP>
__device__ __forceinline__ void panel_mma(
    const float* __restrict__ Asm, const float* __restrict__ Wg,
    float (&acc)[2][4][4], int mc, int npBase, int lane, bool active)
{
#pragma unroll
    for (int f=0; f<2; f++)
#pragma unroll
        for (int j=0; j<4; j++)
#pragma unroll
            for (int e=0; e<4; e++) acc[f][j][e] = 0.f;

    __syncthreads();   // prior epilogue/staging writes visible before A reads
    if (!active) return;

    const float* Ar = Asm + (mc*64 + lane)*4;        // per-kc stride 512
    const float* Wp = Wg + (npBase*32 + lane)*4;     // per-kc stride NTP*128

    float4 nb0 = *(const float4*)Wp;
    float4 nb1 = *(const float4*)(Wp + 128);

#pragma unroll 4
    for (int kc=0; kc<NKC; kc++){
        float4 b0 = nb0, b1 = nb1;
        if (kc+1 < NKC){
            const float* Wn = Wp + (size_t)(kc+1)*(NTP*128);
            nb0 = *(const float4*)Wn;
            nb1 = *(const float4*)(Wn + 128);
        }
        float4 a0v = *(const float4*)(Ar + kc*512);
        float4 a1v = *(const float4*)(Ar + kc*512 + 128);
        u32 a0[4] = {__float_as_uint(a0v.x), __float_as_uint(a0v.y),
                     __float_as_uint(a0v.z), __float_as_uint(a0v.w)};
        u32 a1[4] = {__float_as_uint(a1v.x), __float_as_uint(a1v.y),
                     __float_as_uint(a1v.z), __float_as_uint(a1v.w)};
        mma8(acc[0][0], a0, __float_as_uint(b0.x), __float_as_uint(b0.y));
        mma8(acc[0][1], a0, __float_as_uint(b0.z), __float_as_uint(b0.w));
        mma8(acc[0][2], a0, __float_as_uint(b1.x), __float_as_uint(b1.y));
        mma8(acc[0][3], a0, __float_as_uint(b1.z), __float_as_uint(b1.w));
        mma8(acc[1][0], a1, __float_as_uint(b0.x), __float_as_uint(b0.y));
        mma8(acc[1][1], a1, __float_as_uint(b0.z), __float_as_uint(b0.w));
        mma8(acc[1][2], a1, __float_as_uint(b1.x), __float_as_uint(b1.y));
        mma8(acc[1][3], a1, __float_as_uint(b1.z), __float_as_uint(b1.w));
    }
}

// ---------------- LSTM epilogue (warp tile 32x32, gate-interleaved) -------
__device__ __forceinline__ void epi_lstm(
    float (&acc)[2][4][4], int p, int nc, int mc,
    const float* __restrict__ bb, float* __restrict__ cG, float* __restrict__ hG,
    float* __restrict__ smDst, int kOff, int row0, int lane)
{
    int odd = lane & 1;
#pragma unroll
    for (int fm=0; fm<2; fm++){
        int rbase = mc*32 + fm*16 + (lane>>2);
#pragma unroll
        for (int j=0; j<4; j++){
            float e0 = __shfl_xor_sync(0xFFFFFFFFu, acc[fm][j][0], 1);
            float e1 = __shfl_xor_sync(0xFFFFFFFFu, acc[fm][j][1], 1);
            float e2 = __shfl_xor_sync(0xFFFFFFFFu, acc[fm][j][2], 1);
            float e3 = __shfl_xor_sync(0xFFFFFFFFu, acc[fm][j][3], 1);
            float zi = odd ? e2 : acc[fm][j][0];
            float zf = odd ? e3 : acc[fm][j][1];
            float zg = odd ? acc[fm][j][2] : e0;
            float zo = odd ? acc[fm][j][3] : e1;
            int r = rbase + (odd ? 8 : 0);
            int u = p*64 + nc*8 + j*2 + ((lane&3)>>1);
            if (u < H){
                float4 b = *(const float4*)(bb + u*4);     // i,f,g,o
                size_t gix = (size_t)u*BB + row0 + r;
                float c = cG[gix];
                float cn = sigf(zf + b.y)*c + sigf(zi + b.x)*tanhff(zg + b.z);
                float hn = sigf(zo + b.w)*tanhff(cn);
                cG[gix] = cn; hG[gix] = hn;
                smDst[aidx(kOff + u, r)] = t32(hn);
            }
        }
    }
}

// ---------------- fused per-timestep kernel -------------------------------
__global__ void __launch_bounds__(NTH, 1)
step_kernel(const float* __restrict__ tact, const float* __restrict__ act,
            float* __restrict__ out, int t, int outFrame, int useFb)
{
    extern __shared__ __align__(16) float sm[];
    float* AsX = sm;                 // 256k x 64m frag = 16384 floats
    float* As2 = sm + 16384;         // 448k x 64m frag = 28672 floats

    int tid = threadIdx.x, w = tid>>5, lane = tid&31;
    int mc = w & 1, nc = w >> 1;     // 2 x 8 warp grid
    int row0 = blockIdx.x * MT;

    // -------- staging (t32-rounded) --------
    for (int i=tid; i<512; i+=NTH) AsX[i] = 0.f;   // kc0 pad = zeros
    if (useFb){
        for (int i=tid; i<DT*MT; i+=NTH){
            int d=i>>6, r=i&63;
            AsX[aidx(8+d, r)] = t32(g_x1fb[(size_t)d*BB + row0 + r]);
        }
    } else {
        for (int i=tid; i<DT*MT; i+=NTH){
            int d=i>>6, r=i&63;
            AsX[aidx(8+d, r)] = t32(tact[((size_t)t*BB + row0 + r)*DT + d]);
        }
    }
    for (int i=tid; i<H*MT; i+=NTH){
        int u=i>>6, r=i&63;
        AsX[aidx(56+u, r)] = t32(g_h1[(size_t)u*BB + row0 + r]);
    }
    for (int i=tid; i<DT*MT; i+=NTH){
        int j=i>>6, r=i&63, jm=j%12;
        size_t row = (size_t)row0 + r;
        float v = (jm<6) ? act[((size_t)(t+1)*BB + row)*DA + jm]
                         : act[row*DA + jm - 6];
        As2[aidx(200+j, r)] = t32(v);
    }
    for (int i=tid; i<H*MT; i+=NTH){
        int u=i>>6, r=i&63;
        As2[aidx(248+u, r)] = t32(g_h2[(size_t)u*BB + row0 + r]);
    }

    float acc[2][4][4];

    // -------- stage 1: z1 + LSTM1 (h1' -> As2 k=u) --------
    for (int p=0; p<4; p++){
        panel_mma<32,16>(AsX, g_WAf + (size_t)p*32*32*64,
                         acc, mc, nc*2, lane, true);
        epi_lstm(acc, p, nc, mc, g_bb1, g_c1, g_h1, As2, 0, row0, lane);
    }
    // -------- stage 2: z2 + LSTM2 (h2' -> AsX k=56+u) --------
    for (int p=0; p<4; p++){
        panel_mma<56,16>(As2, g_WBf + (size_t)p*56*32*64,
                         acc, mc, nc*2, lane, true);
        epi_lstm(acc, p, nc, mc, g_bb2, g_c2, g_h2, AsX, 56, row0, lane);
    }
    // -------- stage 3: fc1 + tanh (out3 -> As2 k=n) --------
    {
        panel_mma<32,16>(AsX, g_WCf, acc, mc, nc*2, lane, true);
#pragma unroll
        for (int fm=0; fm<2; fm++){
            int rb = mc*32 + fm*16 + (lane>>2);
#pragma unroll
            for (int j=0; j<4; j++){
                int nb = nc*32 + j*8 + (lane&3)*2;
#pragma unroll
                for (int q=0; q<4; q++){
                    int n = nb + (q&1);
                    int rr = rb + (q>>1)*8;
                    if (n < 224)
                        As2[aidx(n, rr)] = t32(tanhff(acc[fm][j][q] + g_b1p[n]));
                }
            }
        }
    }
    // -------- stage 4: fc2 + tanh -> out + feedback --------
    {
        float acc4[2][4][4];
        panel_mma<28,4>(As2, g_WDf, acc4, mc, nc*2, lane, nc < 2);
        if (nc < 2){
#pragma unroll
            for (int fm=0; fm<2; fm++){
                int rb = mc*32 + fm*16 + (lane>>2);
#pragma unroll
                for (int j=0; j<4; j++){
                    int nb = nc*32 + j*8 + (lane&3)*2;
#pragma unroll
                    for (int q=0; q<4; q++){
                        int n = nb + (q&1);
                        int rr = rb + (q>>1)*8;
                        if (n < DT){
                            float v = tanhff(acc4[fm][j][q] + g_b2p[n]);
                            size_t grow = (size_t)row0 + rr;
                            if (outFrame >= 0)
                                out[((size_t)outFrame*BB + grow)*DT + n] = v;
                            g_x1fb[(size_t)n*BB + grow] = v;
                        }
                    }
                }
            }
        }
    }
}

// ---------------- host launcher -------------------------------------------
#define SMEM_BYTES ((16384 + 28672) * 4)

extern "C" void kernel_launch(void* const* d_in, const int* in_sizes, int n_in,
                              void* d_out, int out_size) {
    const float* tactiles = (const float*)d_in[0];
    const float* actions  = (const float*)d_in[1];
    const float* Wih1 = (const float*)d_in[2];
    const float* Whh1 = (const float*)d_in[3];
    const float* bih1 = (const float*)d_in[4];
    const float* bhh1 = (const float*)d_in[5];
    const float* Wih2 = (const float*)d_in[6];
    const float* Whh2 = (const float*)d_in[7];
    const float* bih2 = (const float*)d_in[8];
    const float* bhh2 = (const float*)d_in[9];
    const float* W1   = (const float*)d_in[10];
    const float* b1   = (const float*)d_in[11];
    const float* W2   = (const float*)d_in[12];
    const float* b2   = (const float*)d_in[13];
    float* out = (float*)d_out;

    cudaFuncSetAttribute(step_kernel,
        cudaFuncAttributeMaxDynamicSharedMemorySize, SMEM_BYTES);

    zero_state<<<2048, 256>>>();
    prep<<<512, 256>>>(Wih1, Whh1, bih1, bhh1,
                       Wih2, Whh2, bih2, bhh2, W1, b1, W2, b2);

    for (int t = 0; t < TT - 1; t++) {
        int useFb    = (t >= CF) ? 1 : 0;
        int outFrame = (t >= CF - 1) ? (t - (CF - 1)) : -1;
        step_kernel<<<NCTA, NTH, SMEM_BYTES>>>(
            tactiles, actions, out, t, outFrame, useFb);
    }
}